// round 8
// baseline (speedup 1.0000x reference)
#include <cuda_runtime.h>
#include <cstdint>

#define D        256
#define MAXN     50000
#define MAXE     800000

// ---------------- scratch (no allocations allowed) ----------------
__device__ __align__(16) float g_agg[(size_t)MAXN * D];  // normalized mean-agg
__device__ __align__(16) float g_h[(size_t)MAXN * D];    // hidden activations
__device__ __align__(16) float g_Bt_hi[256 * 512];       // W^T hi plane [n][k]
__device__ __align__(16) float g_Bt_lo[256 * 512];       // W^T lo plane [n][k]
__device__ int g_cnt[MAXN];
__device__ int g_off[MAXN];
__device__ int g_pos[MAXN];
__device__ int g_csr_src[MAXE];
__device__ int g_src[MAXE];
__device__ int g_tgt[MAXE];
__device__ int g_flag;            // 0 => edge dtype int64, nonzero => int32

__device__ __forceinline__ float tf32_rnd(float v) {
    uint32_t u;
    asm("cvt.rna.tf32.f32 %0, %1;" : "=r"(u) : "f"(v));
    return __uint_as_float(u);
}

// ---------------- edge dtype detect + decode ----------------
__global__ void zero_flag_kernel() { g_flag = 0; }

__global__ void detect_kernel(const int* __restrict__ raw, int n_edges) {
    int i = blockIdx.x * blockDim.x + threadIdx.x;
    if (i < n_edges) {
        if (raw[2 * i + 1] != 0) atomicOr(&g_flag, 1);
    }
}

__global__ void extract_kernel(const int* __restrict__ raw,
                               int n_edges, int n_nodes) {
    int e = blockIdx.x * blockDim.x + threadIdx.x;
    if (e >= n_edges) return;
    int s, t;
    if (g_flag == 0) {             // int64 layout: low word of each int64
        s = raw[2 * e];
        t = raw[2 * (n_edges + e)];
    } else {                       // int32 layout
        s = raw[e];
        t = raw[n_edges + e];
    }
    s = min(max(s, 0), n_nodes - 1);
    t = min(max(t, 0), n_nodes - 1);
    g_src[e] = s;
    g_tgt[e] = t;
}

// ---------------- CSR build ----------------
__global__ void zero_cnt_kernel(int n) {
    int i = blockIdx.x * blockDim.x + threadIdx.x;
    if (i < n) g_cnt[i] = 0;
}

__global__ void count_kernel(int n_edges) {
    int e = blockIdx.x * blockDim.x + threadIdx.x;
    if (e < n_edges) atomicAdd(&g_cnt[g_tgt[e]], 1);
}

__global__ void scan_kernel(int n) {
    const int T = 1024;
    __shared__ int sh[T];
    int tid = threadIdx.x;
    int chunk = (n + T - 1) / T;
    int start = tid * chunk;
    int end   = min(start + chunk, n);

    int sum = 0;
    for (int i = start; i < end; i++) sum += g_cnt[i];
    sh[tid] = sum;
    __syncthreads();

    for (int off = 1; off < T; off <<= 1) {
        int v = (tid >= off) ? sh[tid - off] : 0;
        __syncthreads();
        sh[tid] += v;
        __syncthreads();
    }
    int run = (tid == 0) ? 0 : sh[tid - 1];
    for (int i = start; i < end; i++) {
        g_off[i] = run;
        g_pos[i] = run;
        run += g_cnt[i];
    }
}

__global__ void build_kernel(int n_edges) {
    int e = blockIdx.x * blockDim.x + threadIdx.x;
    if (e < n_edges) {
        int p = atomicAdd(&g_pos[g_tgt[e]], 1);
        g_csr_src[p] = g_src[e];
    }
}

// ---------------- gather mean-aggregate: one warp per node ----------------
__global__ void __launch_bounds__(256)
aggregate_kernel(const float* __restrict__ feat, int n_nodes) {
    int warp = (blockIdx.x * blockDim.x + threadIdx.x) >> 5;
    int lane = threadIdx.x & 31;
    if (warp >= n_nodes) return;

    int beg = g_off[warp];
    int deg = g_cnt[warp];

    float4 a0 = make_float4(0.f, 0.f, 0.f, 0.f);
    float4 a1 = make_float4(0.f, 0.f, 0.f, 0.f);
    for (int i = 0; i < deg; i++) {
        int s = __ldg(&g_csr_src[beg + i]);
        const float4* fs = (const float4*)(feat + (size_t)s * D);
        float4 v0 = fs[lane];
        float4 v1 = fs[lane + 32];
        a0.x += v0.x; a0.y += v0.y; a0.z += v0.z; a0.w += v0.w;
        a1.x += v1.x; a1.y += v1.y; a1.z += v1.z; a1.w += v1.w;
    }
    float iv = 1.0f / (float)(deg > 1 ? deg : 1);
    a0.x *= iv; a0.y *= iv; a0.z *= iv; a0.w *= iv;
    a1.x *= iv; a1.y *= iv; a1.z *= iv; a1.w *= iv;

    float4* out = (float4*)(g_agg + (size_t)warp * D);
    out[lane]      = a0;
    out[lane + 32] = a1;
}

// ---------------- W prep: transpose [Wl;Wr] -> K-major [n][k], tf32 split ----
__global__ void prep_w_kernel(const float* __restrict__ Wl,
                              const float* __restrict__ Wr) {
    int tid = blockIdx.x * blockDim.x + threadIdx.x;
    if (tid >= 256 * 512) return;
    int k = tid & 511;
    int n = tid >> 9;
    float v = (k < 256) ? Wl[(size_t)k * 256 + n]
                        : Wr[(size_t)(k - 256) * 256 + n];
    float h = tf32_rnd(v);
    float l = tf32_rnd(v - h);
    g_Bt_hi[(size_t)n * 512 + k] = h;
    g_Bt_lo[(size_t)n * 512 + k] = l;
}

// ---------------- mma.sync tf32 GEMM (3xTF32 compensated) ----------------
// out[row,:] = act( [g_agg | xin][row,:] @ Wt^T + bias ), M tile 128, N=256,
// K=512 over 32 stages of BK=16, double-buffered. 512 thr = 16 warps (4x4),
// warp tile 32x64 via m16n8k8; per k-slice: hi*hi + lo*hi + hi*lo.
#define ASTRIDE 20
#define ABUF    (128 * ASTRIDE)        // 2560 floats
#define BBUF    (256 * ASTRIDE)        // 5120 floats
#define BUF_F   (2 * ABUF + 2 * BBUF)  // 15360 floats
#define GSMEM   (2 * BUF_F * 4)        // 122880 bytes

#define MMA8(cc, a, b0, b1)                                            \
    asm("mma.sync.aligned.m16n8k8.row.col.f32.tf32.tf32.f32 "          \
        "{%0,%1,%2,%3},{%4,%5,%6,%7},{%8,%9},{%0,%1,%2,%3};"           \
        : "+f"(cc[0]), "+f"(cc[1]), "+f"(cc[2]), "+f"(cc[3])           \
        : "r"(a[0]), "r"(a[1]), "r"(a[2]), "r"(a[3]), "r"(b0), "r"(b1))

__global__ void __launch_bounds__(512, 1)
sage_mma_kernel(const float* __restrict__ xin,
                const float* __restrict__ bias,
                float* __restrict__ out,
                int n_nodes, int do_relu) {
    extern __shared__ __align__(16) float sf[];
    const int tid  = threadIdx.x;
    const int lane = tid & 31;
    const int wid  = tid >> 5;
    const int wm   = wid & 3;       // warp row: 4 x 32 = 128
    const int wn   = wid >> 2;      // warp col: 4 x 64 = 256
    const int row0 = blockIdx.x * 128;

    // A loader: thread -> (row = tid>>2, kq = (tid&3)*4)
    const int  arow = tid >> 2;
    const int  akq  = (tid & 3) << 2;
    const int  grow = row0 + arow;
    const bool av   = grow < n_nodes;
    // B loader: thread -> (n = tid&255, plane = tid>>8), 16 k per stage
    const int bn  = tid & 255;
    const int bpl = tid >> 8;
    const float* gB = bpl ? g_Bt_lo : g_Bt_hi;

    float c[2][8][4];
    #pragma unroll
    for (int t = 0; t < 2; t++)
        #pragma unroll
        for (int nt = 0; nt < 8; nt++)
            #pragma unroll
            for (int j = 0; j < 4; j++) c[t][nt][j] = 0.f;

    const int q  = lane >> 2;
    const int kk = lane & 3;

    // ---- stage loader ----
    auto load_stage = [&](int s, int buf) {
        float* Ah = sf + buf * BUF_F;
        float* Al = Ah + ABUF;
        float* Bh = Al + ABUF;
        float* Bl = Bh + BBUF;
        const int kt = s * 16;
        // A: load float4, split hi/lo, vector store
        float4 v = make_float4(0.f, 0.f, 0.f, 0.f);
        if (av) {
            const float* p = (kt < D)
                ? (g_agg + (size_t)grow * D + kt + akq)
                : (xin   + (size_t)grow * D + (kt - D) + akq);
            v = *(const float4*)p;
        }
        float4 h, l;
        h.x = tf32_rnd(v.x); l.x = tf32_rnd(v.x - h.x);
        h.y = tf32_rnd(v.y); l.y = tf32_rnd(v.y - h.y);
        h.z = tf32_rnd(v.z); l.z = tf32_rnd(v.z - h.z);
        h.w = tf32_rnd(v.w); l.w = tf32_rnd(v.w - h.w);
        *(float4*)(Ah + arow * ASTRIDE + akq) = h;
        *(float4*)(Al + arow * ASTRIDE + akq) = l;
        // B: copy 16 k of one (n, plane) row
        const float4* src = (const float4*)(gB + (size_t)bn * 512 + kt);
        float* dst = (bpl ? Bl : Bh) + bn * ASTRIDE;
        float4 b0 = src[0], b1 = src[1], b2 = src[2], b3 = src[3];
        ((float4*)dst)[0] = b0;
        ((float4*)dst)[1] = b1;
        ((float4*)dst)[2] = b2;
        ((float4*)dst)[3] = b3;
    };

    // ---- compute one staged BK=16 ----
    auto compute_stage = [&](int buf) {
        const float* Ah = sf + buf * BUF_F;
        const float* Al = Ah + ABUF;
        const float* Bh = Al + ABUF;
        const float* Bl = Bh + BBUF;
        #pragma unroll
        for (int ks = 0; ks < 2; ks++) {
            const int k0 = ks * 8;
            uint32_t ah[2][4], al[2][4];
            #pragma unroll
            for (int t = 0; t < 2; t++) {
                const int r = wm * 32 + t * 16 + q;
                const uint32_t* ph = (const uint32_t*)(Ah + r * ASTRIDE + k0 + kk);
                const uint32_t* pl = (const uint32_t*)(Al + r * ASTRIDE + k0 + kk);
                ah[t][0] = ph[0];
                ah[t][1] = ph[8 * ASTRIDE];
                ah[t][2] = ph[4];
                ah[t][3] = ph[8 * ASTRIDE + 4];
                al[t][0] = pl[0];
                al[t][1] = pl[8 * ASTRIDE];
                al[t][2] = pl[4];
                al[t][3] = pl[8 * ASTRIDE + 4];
            }
            #pragma unroll
            for (int nt = 0; nt < 8; nt++) {
                const int n = wn * 64 + nt * 8 + q;
                const uint32_t* pb = (const uint32_t*)(Bh + n * ASTRIDE + k0 + kk);
                const uint32_t* qb = (const uint32_t*)(Bl + n * ASTRIDE + k0 + kk);
                uint32_t bh0 = pb[0], bh1 = pb[4];
                uint32_t bl0 = qb[0], bl1 = qb[4];
                #pragma unroll
                for (int t = 0; t < 2; t++) {
                    MMA8(c[t][nt], ah[t], bh0, bh1);
                    MMA8(c[t][nt], al[t], bh0, bh1);
                    MMA8(c[t][nt], ah[t], bl0, bl1);
                }
            }
        }
    };

    load_stage(0, 0);
    __syncthreads();
    #pragma unroll 1
    for (int s = 0; s < 32; s++) {
        if (s + 1 < 32) load_stage(s + 1, (s + 1) & 1);
        compute_stage(s & 1);
        __syncthreads();
    }

    // ---- epilogue: bias (+ReLU), direct global stores ----
    #pragma unroll
    for (int t = 0; t < 2; t++) {
        const int r = row0 + wm * 32 + t * 16 + q;
        #pragma unroll
        for (int nt = 0; nt < 8; nt++) {
            const int col = wn * 64 + nt * 8 + kk * 2;
            float2 b2 = *(const float2*)(bias + col);
            float v0 = c[t][nt][0] + b2.x;
            float v1 = c[t][nt][1] + b2.y;
            float v2 = c[t][nt][2] + b2.x;
            float v3 = c[t][nt][3] + b2.y;
            if (do_relu) {
                v0 = fmaxf(v0, 0.f); v1 = fmaxf(v1, 0.f);
                v2 = fmaxf(v2, 0.f); v3 = fmaxf(v3, 0.f);
            }
            if (r < n_nodes)
                *(float2*)(out + (size_t)r * D + col) = make_float2(v0, v1);
            if (r + 8 < n_nodes)
                *(float2*)(out + (size_t)(r + 8) * D + col) = make_float2(v2, v3);
        }
    }
}

// ---------------- launch ----------------
extern "C" void kernel_launch(void* const* d_in, const int* in_sizes, int n_in,
                              void* d_out, int out_size) {
    const float* x   = (const float*)d_in[0];
    const int*   raw = (const int*)d_in[1];
    const float* W1l = (const float*)d_in[2];
    const float* b1  = (const float*)d_in[3];
    const float* W1r = (const float*)d_in[4];
    const float* W2l = (const float*)d_in[5];
    const float* b2  = (const float*)d_in[6];
    const float* W2r = (const float*)d_in[7];
    float* out = (float*)d_out;

    const int n_nodes = in_sizes[0] / D;
    const int n_edges = in_sizes[1] / 2;

    float* hptr;
    cudaGetSymbolAddress((void**)&hptr, g_h);

    static bool attr_set = false;
    if (!attr_set) {
        cudaFuncSetAttribute(sage_mma_kernel,
                             cudaFuncAttributeMaxDynamicSharedMemorySize,
                             GSMEM);
        attr_set = true;
    }

    const int mma_blocks = (n_nodes + 127) / 128;
    const int agg_blocks = (n_nodes * 32 + 255) / 256;
    const int eb = (n_edges + 255) / 256;
    const int nb = (n_nodes + 255) / 256;
    const int wb = (256 * 512 + 255) / 256;

    // ---- edge dtype detect + decode ----
    zero_flag_kernel<<<1, 1>>>();
    detect_kernel<<<eb, 256>>>(raw, n_edges);
    extract_kernel<<<eb, 256>>>(raw, n_edges, n_nodes);

    // ---- CSR build (reused by both layers) ----
    zero_cnt_kernel<<<nb, 256>>>(n_nodes);
    count_kernel<<<eb, 256>>>(n_edges);
    scan_kernel<<<1, 1024>>>(n_nodes);
    build_kernel<<<eb, 256>>>(n_edges);

    // ---- layer 1 ----
    aggregate_kernel<<<agg_blocks, 256>>>(x, n_nodes);
    prep_w_kernel<<<wb, 256>>>(W1l, W1r);
    sage_mma_kernel<<<mma_blocks, 512, GSMEM>>>(x, b1, hptr, n_nodes, 1);

    // ---- layer 2 ----
    aggregate_kernel<<<agg_blocks, 256>>>(hptr, n_nodes);
    prep_w_kernel<<<wb, 256>>>(W2l, W2r);
    sage_mma_kernel<<<mma_blocks, 512, GSMEM>>>(hptr, b2, out, n_nodes, 0);
}

// round 9
// speedup vs baseline: 1.2461x; 1.2461x over previous
#include <cuda_runtime.h>
#include <cuda_fp16.h>
#include <cstdint>

#define D        256
#define MAXN     50000
#define MAXE     800000

// ---------------- scratch (no allocations allowed) ----------------
__device__ __align__(16) float  g_agg[(size_t)MAXN * D];   // normalized mean-agg
__device__ __align__(16) float  g_h[(size_t)MAXN * D];     // hidden activations
// W^T split planes, fp16, staged layout [kstage][n][16]
__device__ __align__(16) __half g_Bth[256 * 512];
__device__ __align__(16) __half g_Btl[256 * 512];
__device__ int g_cnt[MAXN];
__device__ int g_off[MAXN];
__device__ int g_pos[MAXN];
__device__ int g_csr_src[MAXE];
__device__ int g_src[MAXE];
__device__ int g_tgt[MAXE];
__device__ int g_flag;            // 0 => edge dtype int64, nonzero => int32

__device__ __forceinline__ uint32_t smem_u32(const void* p) {
    uint32_t a;
    asm("{ .reg .u64 t; cvta.to.shared.u64 t, %1; cvt.u32.u64 %0, t; }"
        : "=r"(a) : "l"(p));
    return a;
}

// ---------------- edge dtype detect + decode ----------------
__global__ void zero_flag_kernel() { g_flag = 0; }

__global__ void detect_kernel(const int* __restrict__ raw, int n_edges) {
    int i = blockIdx.x * blockDim.x + threadIdx.x;
    if (i < n_edges) {
        if (raw[2 * i + 1] != 0) atomicOr(&g_flag, 1);
    }
}

__global__ void extract_kernel(const int* __restrict__ raw,
                               int n_edges, int n_nodes) {
    int e = blockIdx.x * blockDim.x + threadIdx.x;
    if (e >= n_edges) return;
    int s, t;
    if (g_flag == 0) {             // int64 layout: low word of each int64
        s = raw[2 * e];
        t = raw[2 * (n_edges + e)];
    } else {                       // int32 layout
        s = raw[e];
        t = raw[n_edges + e];
    }
    s = min(max(s, 0), n_nodes - 1);
    t = min(max(t, 0), n_nodes - 1);
    g_src[e] = s;
    g_tgt[e] = t;
}

// ---------------- CSR build ----------------
__global__ void zero_cnt_kernel(int n) {
    int i = blockIdx.x * blockDim.x + threadIdx.x;
    if (i < n) g_cnt[i] = 0;
}

__global__ void count_kernel(int n_edges) {
    int e = blockIdx.x * blockDim.x + threadIdx.x;
    if (e < n_edges) atomicAdd(&g_cnt[g_tgt[e]], 1);
}

__global__ void scan_kernel(int n) {
    const int T = 1024;
    __shared__ int sh[T];
    int tid = threadIdx.x;
    int chunk = (n + T - 1) / T;
    int start = tid * chunk;
    int end   = min(start + chunk, n);

    int sum = 0;
    for (int i = start; i < end; i++) sum += g_cnt[i];
    sh[tid] = sum;
    __syncthreads();

    for (int off = 1; off < T; off <<= 1) {
        int v = (tid >= off) ? sh[tid - off] : 0;
        __syncthreads();
        sh[tid] += v;
        __syncthreads();
    }
    int run = (tid == 0) ? 0 : sh[tid - 1];
    for (int i = start; i < end; i++) {
        g_off[i] = run;
        g_pos[i] = run;
        run += g_cnt[i];
    }
}

__global__ void build_kernel(int n_edges) {
    int e = blockIdx.x * blockDim.x + threadIdx.x;
    if (e < n_edges) {
        int p = atomicAdd(&g_pos[g_tgt[e]], 1);
        g_csr_src[p] = g_src[e];
    }
}

// ---------------- gather mean-aggregate: one warp per node ----------------
__global__ void __launch_bounds__(256)
aggregate_kernel(const float* __restrict__ feat, int n_nodes) {
    int warp = (blockIdx.x * blockDim.x + threadIdx.x) >> 5;
    int lane = threadIdx.x & 31;
    if (warp >= n_nodes) return;

    int beg = g_off[warp];
    int deg = g_cnt[warp];

    float4 a0 = make_float4(0.f, 0.f, 0.f, 0.f);
    float4 a1 = make_float4(0.f, 0.f, 0.f, 0.f);
    float4 c0 = make_float4(0.f, 0.f, 0.f, 0.f);
    float4 c1 = make_float4(0.f, 0.f, 0.f, 0.f);
    int i = 0;
    for (; i + 2 <= deg; i += 2) {
        int s0 = __ldg(&g_csr_src[beg + i]);
        int s1 = __ldg(&g_csr_src[beg + i + 1]);
        const float4* f0 = (const float4*)(feat + (size_t)s0 * D);
        const float4* f1 = (const float4*)(feat + (size_t)s1 * D);
        float4 v0 = f0[lane];
        float4 v1 = f0[lane + 32];
        float4 v2 = f1[lane];
        float4 v3 = f1[lane + 32];
        a0.x += v0.x; a0.y += v0.y; a0.z += v0.z; a0.w += v0.w;
        a1.x += v1.x; a1.y += v1.y; a1.z += v1.z; a1.w += v1.w;
        c0.x += v2.x; c0.y += v2.y; c0.z += v2.z; c0.w += v2.w;
        c1.x += v3.x; c1.y += v3.y; c1.z += v3.z; c1.w += v3.w;
    }
    if (i < deg) {
        int s0 = __ldg(&g_csr_src[beg + i]);
        const float4* f0 = (const float4*)(feat + (size_t)s0 * D);
        float4 v0 = f0[lane];
        float4 v1 = f0[lane + 32];
        a0.x += v0.x; a0.y += v0.y; a0.z += v0.z; a0.w += v0.w;
        a1.x += v1.x; a1.y += v1.y; a1.z += v1.z; a1.w += v1.w;
    }
    a0.x += c0.x; a0.y += c0.y; a0.z += c0.z; a0.w += c0.w;
    a1.x += c1.x; a1.y += c1.y; a1.z += c1.z; a1.w += c1.w;

    float iv = 1.0f / (float)(deg > 1 ? deg : 1);
    a0.x *= iv; a0.y *= iv; a0.z *= iv; a0.w *= iv;
    a1.x *= iv; a1.y *= iv; a1.z *= iv; a1.w *= iv;

    float4* outp = (float4*)(g_agg + (size_t)warp * D);
    outp[lane]      = a0;
    outp[lane + 32] = a1;
}

// ---------------- W prep: [Wl;Wr]^T -> fp16 hi/lo, layout [kstage][n][16] ----
__global__ void prep_w_kernel(const float* __restrict__ Wl,
                              const float* __restrict__ Wr) {
    int tid = blockIdx.x * blockDim.x + threadIdx.x;
    if (tid >= 256 * 512) return;
    int k = tid & 511;
    int n = tid >> 9;
    float v = (k < 256) ? Wl[(size_t)k * 256 + n]
                        : Wr[(size_t)(k - 256) * 256 + n];
    __half h = __float2half_rn(v);
    __half l = __float2half_rn(v - __half2float(h));
    int off = (k >> 4) * 4096 + n * 16 + (k & 15);
    g_Bth[off] = h;
    g_Btl[off] = l;
}

// ---------------- mma.sync fp16-split GEMM (3 passes, fp32 accum) ----------
// out[row,:] = act( [g_agg | xin][row,:] @ W + bias ),  K=512, 32 stages BK=16.
// CTA tile 128x128 (grid 391 x 2), 512 thr = 16 warps (4x4), warp tile 32x32.
// SMEM stage (24KB x2): A_hi[128][24] A_lo B_hi[128][24] B_lo (fp16, 48B rows).
#define STAGE_B 24576

#define LDSM4(r, addr)                                                      \
    asm volatile("ldmatrix.sync.aligned.m8n8.x4.shared.b16 "                \
                 "{%0,%1,%2,%3}, [%4];"                                     \
                 : "=r"((r)[0]), "=r"((r)[1]), "=r"((r)[2]), "=r"((r)[3])   \
                 : "r"(addr))

#define MMA16(cc, a, b0, b1)                                                \
    asm volatile("mma.sync.aligned.m16n8k16.row.col.f32.f16.f16.f32 "       \
                 "{%0,%1,%2,%3},{%4,%5,%6,%7},{%8,%9},{%0,%1,%2,%3};"       \
                 : "+f"((cc)[0]), "+f"((cc)[1]), "+f"((cc)[2]), "+f"((cc)[3]) \
                 : "r"((a)[0]), "r"((a)[1]), "r"((a)[2]), "r"((a)[3]),      \
                   "r"(b0), "r"(b1))

__global__ void __launch_bounds__(512, 1)
sage_mma_kernel(const float* __restrict__ xin,
                const float* __restrict__ bias,
                float* __restrict__ out,
                int n_nodes, int do_relu) {
    extern __shared__ __align__(1024) char sm[];
    const uint32_t smb = smem_u32(sm);
    const int tid   = threadIdx.x;
    const int lane  = tid & 31;
    const int wid   = tid >> 5;
    const int wm    = wid & 3;
    const int wn    = wid >> 2;
    const int row0  = blockIdx.x * 128;
    const int ncol0 = blockIdx.y * 128;

    // A staging: thread -> (row = tid>>2, kq = (tid&3)*4)
    const int  arow = tid >> 2;
    const int  akq  = (tid & 3) << 2;
    const int  grow = row0 + arow;
    const bool av   = grow < n_nodes;
    // B staging: thread -> one 16B cp.async chunk
    const int bpl   = tid >> 8;
    const int bn_   = (tid & 255) >> 1;
    const int bhalf = tid & 1;
    const __half* gBsrc = (bpl ? g_Btl : g_Bth)
                        + (size_t)(ncol0 + bn_) * 16 + bhalf * 8;
    const uint32_t bdst = 12288u + bpl * 6144u + bn_ * 48u + bhalf * 16u;

    // ldmatrix lane addresses (byte offsets within a plane)
    const int aRow = wm * 32 + (lane & 7) + 8 * ((lane >> 3) & 1);
    const uint32_t aOff = aRow * 48 + ((lane >> 4) << 4);
    const int bRow = wn * 32 + ((lane >> 4) << 3) + (lane & 7);
    const uint32_t bOff = bRow * 48 + (((lane >> 3) & 1) << 4);

    float c[2][4][4];
    #pragma unroll
    for (int t = 0; t < 2; t++)
        #pragma unroll
        for (int nt = 0; nt < 4; nt++)
            #pragma unroll
            for (int j = 0; j < 4; j++) c[t][nt][j] = 0.f;

    // ---- stage issue: cp.async B chunk + A split/store ----
    auto issue = [&](int s, int buf) {
        const uint32_t bb = smb + buf * STAGE_B;
        asm volatile("cp.async.ca.shared.global [%0], [%1], 16;"
                     :: "r"(bb + bdst), "l"(gBsrc + (size_t)s * 4096)
                     : "memory");
        const int kt = s * 16;
        float4 v = make_float4(0.f, 0.f, 0.f, 0.f);
        if (av) {
            const float* p = (kt < D)
                ? (g_agg + (size_t)grow * D + kt + akq)
                : (xin   + (size_t)grow * D + (kt - D) + akq);
            v = *(const float4*)p;
        }
        __half hx = __float2half_rn(v.x), hy = __float2half_rn(v.y);
        __half hz = __float2half_rn(v.z), hw = __float2half_rn(v.w);
        __half lx = __float2half_rn(v.x - __half2float(hx));
        __half ly = __float2half_rn(v.y - __half2float(hy));
        __half lz = __float2half_rn(v.z - __half2float(hz));
        __half lw = __float2half_rn(v.w - __half2float(hw));
        uint32_t h01 = (uint32_t)__half_as_ushort(hx) |
                       ((uint32_t)__half_as_ushort(hy) << 16);
        uint32_t h23 = (uint32_t)__half_as_ushort(hz) |
                       ((uint32_t)__half_as_ushort(hw) << 16);
        uint32_t l01 = (uint32_t)__half_as_ushort(lx) |
                       ((uint32_t)__half_as_ushort(ly) << 16);
        uint32_t l23 = (uint32_t)__half_as_ushort(lz) |
                       ((uint32_t)__half_as_ushort(lw) << 16);
        const uint32_t ad = bb + arow * 48 + (akq << 1);
        asm volatile("st.shared.v2.b32 [%0], {%1,%2};"
                     :: "r"(ad), "r"(h01), "r"(h23) : "memory");
        asm volatile("st.shared.v2.b32 [%0], {%1,%2};"
                     :: "r"(ad + 6144), "r"(l01), "r"(l23) : "memory");
    };

    // ---- compute one BK=16 stage ----
    auto compute = [&](int buf) {
        const uint32_t bb = smb + buf * STAGE_B;
        uint32_t ah[2][4], al[2][4], bf[2][4];
        LDSM4(ah[0], bb + aOff);
        LDSM4(ah[1], bb + aOff + 768);
        LDSM4(al[0], bb + 6144 + aOff);
        LDSM4(al[1], bb + 6144 + aOff + 768);
        LDSM4(bf[0], bb + 12288 + bOff);
        LDSM4(bf[1], bb + 12288 + bOff + 768);
        #pragma unroll
        for (int t = 0; t < 2; t++)
            #pragma unroll
            for (int nt = 0; nt < 4; nt++) {
                uint32_t b0 = bf[nt >> 1][(nt & 1) * 2];
                uint32_t b1 = bf[nt >> 1][(nt & 1) * 2 + 1];
                MMA16(c[t][nt], ah[t], b0, b1);
                MMA16(c[t][nt], al[t], b0, b1);
            }
        LDSM4(bf[0], bb + 18432 + bOff);
        LDSM4(bf[1], bb + 18432 + bOff + 768);
        #pragma unroll
        for (int t = 0; t < 2; t++)
            #pragma unroll
            for (int nt = 0; nt < 4; nt++) {
                uint32_t b0 = bf[nt >> 1][(nt & 1) * 2];
                uint32_t b1 = bf[nt >> 1][(nt & 1) * 2 + 1];
                MMA16(c[t][nt], ah[t], b0, b1);
            }
    };

    issue(0, 0);
    asm volatile("cp.async.commit_group;" ::: "memory");
    #pragma unroll 1
    for (int s = 0; s < 32; s++) {
        if (s + 1 < 32) {
            issue(s + 1, (s + 1) & 1);
            asm volatile("cp.async.commit_group;" ::: "memory");
            asm volatile("cp.async.wait_group 1;" ::: "memory");
        } else {
            asm volatile("cp.async.wait_group 0;" ::: "memory");
        }
        __syncthreads();
        compute(s & 1);
        __syncthreads();
    }

    // ---- epilogue: bias (+ReLU), direct global stores ----
    #pragma unroll
    for (int t = 0; t < 2; t++) {
        const int r1 = row0 + wm * 32 + t * 16 + (lane >> 2);
        #pragma unroll
        for (int nt = 0; nt < 4; nt++) {
            const int col = ncol0 + wn * 32 + nt * 8 + 2 * (lane & 3);
            float2 b2 = *(const float2*)(bias + col);
            float v0 = c[t][nt][0] + b2.x;
            float v1 = c[t][nt][1] + b2.y;
            float v2 = c[t][nt][2] + b2.x;
            float v3 = c[t][nt][3] + b2.y;
            if (do_relu) {
                v0 = fmaxf(v0, 0.f); v1 = fmaxf(v1, 0.f);
                v2 = fmaxf(v2, 0.f); v3 = fmaxf(v3, 0.f);
            }
            if (r1 < n_nodes)
                *(float2*)(out + (size_t)r1 * D + col) = make_float2(v0, v1);
            if (r1 + 8 < n_nodes)
                *(float2*)(out + (size_t)(r1 + 8) * D + col) = make_float2(v2, v3);
        }
    }
}

// ---------------- launch ----------------
extern "C" void kernel_launch(void* const* d_in, const int* in_sizes, int n_in,
                              void* d_out, int out_size) {
    const float* x   = (const float*)d_in[0];
    const int*   raw = (const int*)d_in[1];
    const float* W1l = (const float*)d_in[2];
    const float* b1  = (const float*)d_in[3];
    const float* W1r = (const float*)d_in[4];
    const float* W2l = (const float*)d_in[5];
    const float* b2  = (const float*)d_in[6];
    const float* W2r = (const float*)d_in[7];
    float* out = (float*)d_out;

    const int n_nodes = in_sizes[0] / D;
    const int n_edges = in_sizes[1] / 2;

    float* hptr;
    cudaGetSymbolAddress((void**)&hptr, g_h);

    const dim3 mma_grid((n_nodes + 127) / 128, 2);
    const int agg_blocks = (n_nodes * 32 + 255) / 256;
    const int eb = (n_edges + 255) / 256;
    const int nb = (n_nodes + 255) / 256;
    const int wb = (256 * 512 + 255) / 256;
    const int smem = 2 * STAGE_B;   // 48 KB (within default dynamic limit)

    // ---- edge dtype detect + decode ----
    zero_flag_kernel<<<1, 1>>>();
    detect_kernel<<<eb, 256>>>(raw, n_edges);
    extract_kernel<<<eb, 256>>>(raw, n_edges, n_nodes);

    // ---- CSR build (reused by both layers) ----
    zero_cnt_kernel<<<nb, 256>>>(n_nodes);
    count_kernel<<<eb, 256>>>(n_edges);
    scan_kernel<<<1, 1024>>>(n_nodes);
    build_kernel<<<eb, 256>>>(n_edges);

    // ---- layer 1 ----
    aggregate_kernel<<<agg_blocks, 256>>>(x, n_nodes);
    prep_w_kernel<<<wb, 256>>>(W1l, W1r);
    sage_mma_kernel<<<mma_grid, 512, smem>>>(x, b1, hptr, n_nodes, 1);

    // ---- layer 2 ----
    aggregate_kernel<<<agg_blocks, 256>>>(hptr, n_nodes);
    prep_w_kernel<<<wb, 256>>>(W2l, W2r);
    sage_mma_kernel<<<mma_grid, 512, smem>>>(hptr, b2, out, n_nodes, 0);
}

// round 10
// speedup vs baseline: 1.7809x; 1.4292x over previous
#include <cuda_runtime.h>
#include <cuda_fp16.h>
#include <cstdint>

#define D     256
#define MAXN  50000
#define NPAD  50048
#define MAXE  800000

// ---------------- scratch (no allocations allowed) ----------------
__device__ __align__(16) float  g_h[(size_t)MAXN * D];   // hidden activations (fp32)
__device__ __align__(16) __half g_Bth[256 * 512];        // B hi, staged [s][n][16]
__device__ __align__(16) __half g_Btl[256 * 512];        // B lo
// A-half fp16 planes, staged [s<16][row][16] (dense, NPAD rows)
__device__ __align__(16) __half g_AGh[(size_t)16 * NPAD * 16];  // agg hi
__device__ __align__(16) __half g_AGl[(size_t)16 * NPAD * 16];  // agg lo
__device__ __align__(16) __half g_Xh [(size_t)16 * NPAD * 16];  // x hi
__device__ __align__(16) __half g_Xl [(size_t)16 * NPAD * 16];  // x lo
__device__ __align__(16) __half g_Hh [(size_t)16 * NPAD * 16];  // h hi
__device__ __align__(16) __half g_Hl [(size_t)16 * NPAD * 16];  // h lo
__device__ int g_cnt[MAXN];
__device__ int g_off[MAXN];
__device__ int g_pos[MAXN];
__device__ int g_csr_src[MAXE];
__device__ int g_src[MAXE];
__device__ int g_tgt[MAXE];
__device__ int g_flag;            // 0 => edge dtype int64, nonzero => int32

__device__ __forceinline__ uint32_t smem_u32(const void* p) {
    uint32_t a;
    asm("{ .reg .u64 t; cvta.to.shared.u64 t, %1; cvt.u32.u64 %0, t; }"
        : "=r"(a) : "l"(p));
    return a;
}
__device__ __forceinline__ void split2(float v, __half& h, __half& l) {
    h = __float2half_rn(v);
    l = __float2half_rn(v - __half2float(h));
}
__device__ __forceinline__ uint2 pack4(__half a, __half b, __half c, __half d) {
    uint2 r;
    r.x = (uint32_t)__half_as_ushort(a) | ((uint32_t)__half_as_ushort(b) << 16);
    r.y = (uint32_t)__half_as_ushort(c) | ((uint32_t)__half_as_ushort(d) << 16);
    return r;
}

// ---------------- edge dtype detect + decode ----------------
__global__ void zero_flag_kernel() { g_flag = 0; }

__global__ void detect_kernel(const int* __restrict__ raw, int n_edges) {
    int i = blockIdx.x * blockDim.x + threadIdx.x;
    if (i < n_edges) {
        if (raw[2 * i + 1] != 0) atomicOr(&g_flag, 1);
    }
}

__global__ void extract_kernel(const int* __restrict__ raw,
                               int n_edges, int n_nodes) {
    int e = blockIdx.x * blockDim.x + threadIdx.x;
    if (e >= n_edges) return;
    int s, t;
    if (g_flag == 0) {             // int64 layout: low word of each int64
        s = raw[2 * e];
        t = raw[2 * (n_edges + e)];
    } else {                       // int32 layout
        s = raw[e];
        t = raw[n_edges + e];
    }
    s = min(max(s, 0), n_nodes - 1);
    t = min(max(t, 0), n_nodes - 1);
    g_src[e] = s;
    g_tgt[e] = t;
}

// ---------------- CSR build ----------------
__global__ void zero_cnt_kernel(int n) {
    int i = blockIdx.x * blockDim.x + threadIdx.x;
    if (i < n) g_cnt[i] = 0;
}

__global__ void count_kernel(int n_edges) {
    int e = blockIdx.x * blockDim.x + threadIdx.x;
    if (e < n_edges) atomicAdd(&g_cnt[g_tgt[e]], 1);
}

__global__ void scan_kernel(int n) {
    const int T = 1024;
    __shared__ int sh[T];
    int tid = threadIdx.x;
    int chunk = (n + T - 1) / T;
    int start = tid * chunk;
    int end   = min(start + chunk, n);

    int sum = 0;
    for (int i = start; i < end; i++) sum += g_cnt[i];
    sh[tid] = sum;
    __syncthreads();

    for (int off = 1; off < T; off <<= 1) {
        int v = (tid >= off) ? sh[tid - off] : 0;
        __syncthreads();
        sh[tid] += v;
        __syncthreads();
    }
    int run = (tid == 0) ? 0 : sh[tid - 1];
    for (int i = start; i < end; i++) {
        g_off[i] = run;
        g_pos[i] = run;
        run += g_cnt[i];
    }
}

__global__ void build_kernel(int n_edges) {
    int e = blockIdx.x * blockDim.x + threadIdx.x;
    if (e < n_edges) {
        int p = atomicAdd(&g_pos[g_tgt[e]], 1);
        g_csr_src[p] = g_src[e];
    }
}

// ---------------- gather mean-aggregate -> fp16 hi/lo staged planes --------
__global__ void __launch_bounds__(256)
aggregate_kernel(const float* __restrict__ feat, int n_nodes) {
    int warp = (blockIdx.x * blockDim.x + threadIdx.x) >> 5;
    int lane = threadIdx.x & 31;
    if (warp >= n_nodes) return;

    int beg = g_off[warp];
    int deg = g_cnt[warp];

    float4 a0 = make_float4(0.f, 0.f, 0.f, 0.f);
    float4 a1 = make_float4(0.f, 0.f, 0.f, 0.f);
    float4 c0 = make_float4(0.f, 0.f, 0.f, 0.f);
    float4 c1 = make_float4(0.f, 0.f, 0.f, 0.f);
    int i = 0;
    for (; i + 2 <= deg; i += 2) {
        int s0 = __ldg(&g_csr_src[beg + i]);
        int s1 = __ldg(&g_csr_src[beg + i + 1]);
        const float4* f0 = (const float4*)(feat + (size_t)s0 * D);
        const float4* f1 = (const float4*)(feat + (size_t)s1 * D);
        float4 v0 = f0[lane];
        float4 v1 = f0[lane + 32];
        float4 v2 = f1[lane];
        float4 v3 = f1[lane + 32];
        a0.x += v0.x; a0.y += v0.y; a0.z += v0.z; a0.w += v0.w;
        a1.x += v1.x; a1.y += v1.y; a1.z += v1.z; a1.w += v1.w;
        c0.x += v2.x; c0.y += v2.y; c0.z += v2.z; c0.w += v2.w;
        c1.x += v3.x; c1.y += v3.y; c1.z += v3.z; c1.w += v3.w;
    }
    if (i < deg) {
        int s0 = __ldg(&g_csr_src[beg + i]);
        const float4* f0 = (const float4*)(feat + (size_t)s0 * D);
        float4 v0 = f0[lane];
        float4 v1 = f0[lane + 32];
        a0.x += v0.x; a0.y += v0.y; a0.z += v0.z; a0.w += v0.w;
        a1.x += v1.x; a1.y += v1.y; a1.z += v1.z; a1.w += v1.w;
    }
    a0.x += c0.x; a0.y += c0.y; a0.z += c0.z; a0.w += c0.w;
    a1.x += c1.x; a1.y += c1.y; a1.z += c1.z; a1.w += c1.w;

    float iv = 1.0f / (float)(deg > 1 ? deg : 1);
    a0.x *= iv; a0.y *= iv; a0.z *= iv; a0.w *= iv;
    a1.x *= iv; a1.y *= iv; a1.z *= iv; a1.w *= iv;

    // write staged fp16 hi/lo: lane covers k0=4*lane (a0) and k1=128+4*lane (a1)
    const int sp = lane >> 2;
    const int kk = (lane & 3) * 4;
    size_t off0 = ((size_t)sp * NPAD + warp) * 16 + kk;
    size_t off1 = ((size_t)(8 + sp) * NPAD + warp) * 16 + kk;
    __half h0, l0, h1, l1, h2, l2, h3, l3;
    split2(a0.x, h0, l0); split2(a0.y, h1, l1);
    split2(a0.z, h2, l2); split2(a0.w, h3, l3);
    *(uint2*)(g_AGh + off0) = pack4(h0, h1, h2, h3);
    *(uint2*)(g_AGl + off0) = pack4(l0, l1, l2, l3);
    split2(a1.x, h0, l0); split2(a1.y, h1, l1);
    split2(a1.z, h2, l2); split2(a1.w, h3, l3);
    *(uint2*)(g_AGh + off1) = pack4(h0, h1, h2, h3);
    *(uint2*)(g_AGl + off1) = pack4(l0, l1, l2, l3);
}

// ---------------- one-time x -> staged fp16 hi/lo planes ----------------
__global__ void convert_x_kernel(const float* __restrict__ x, int n_nodes) {
    int t = blockIdx.x * blockDim.x + threadIdx.x;
    if (t >= n_nodes * 64) return;
    int row = t >> 6;
    int g   = t & 63;                  // k0 = 4g
    float4 v = *(const float4*)(x + (size_t)row * D + g * 4);
    __half h0, l0, h1, l1, h2, l2, h3, l3;
    split2(v.x, h0, l0); split2(v.y, h1, l1);
    split2(v.z, h2, l2); split2(v.w, h3, l3);
    size_t off = ((size_t)(g >> 2) * NPAD + row) * 16 + (g & 3) * 4;
    *(uint2*)(g_Xh + off) = pack4(h0, h1, h2, h3);
    *(uint2*)(g_Xl + off) = pack4(l0, l1, l2, l3);
}

// ---------------- W prep: [Wl;Wr]^T -> fp16 hi/lo, staged [s][n][16] -------
__global__ void prep_w_kernel(const float* __restrict__ Wl,
                              const float* __restrict__ Wr) {
    int tid = blockIdx.x * blockDim.x + threadIdx.x;
    if (tid >= 256 * 512) return;
    int k = tid & 511;
    int n = tid >> 9;
    float v = (k < 256) ? Wl[(size_t)k * 256 + n]
                        : Wr[(size_t)(k - 256) * 256 + n];
    __half h, l;
    split2(v, h, l);
    int off = (k >> 4) * 4096 + n * 16 + (k & 15);
    g_Bth[off] = h;
    g_Btl[off] = l;
}

// ---------------- mma.sync fp16-split GEMM (3 passes, fp32 accum) ----------
// out[row,:] = act( [agg | input][row,:] @ W + bias ). CTA 128x256, K=512,
// 32 stages BK=16, 512 thr = 16 warps (4x4), warp tile 32x64.
// Stage smem: Ah[128][24h] Al Bh[256][24h] Bl (48B rows) = 36864B, x2 buffers.
// One __syncthreads per stage; LDG for s+2 issued under compute(s).
#define STAGE_B 36864

#define LDSM4(r, addr)                                                      \
    asm volatile("ldmatrix.sync.aligned.m8n8.x4.shared.b16 "                \
                 "{%0,%1,%2,%3}, [%4];"                                     \
                 : "=r"((r)[0]), "=r"((r)[1]), "=r"((r)[2]), "=r"((r)[3])   \
                 : "r"(addr))

#define MMA16(cc, a, b0, b1)                                                \
    asm volatile("mma.sync.aligned.m16n8k16.row.col.f32.f16.f16.f32 "       \
                 "{%0,%1,%2,%3},{%4,%5,%6,%7},{%8,%9},{%0,%1,%2,%3};"       \
                 : "+f"((cc)[0]), "+f"((cc)[1]), "+f"((cc)[2]), "+f"((cc)[3]) \
                 : "r"((a)[0]), "r"((a)[1]), "r"((a)[2]), "r"((a)[3]),      \
                   "r"(b0), "r"(b1))

__global__ void __launch_bounds__(512, 1)
sage_mma_kernel(const __half* __restrict__ inh, const __half* __restrict__ inl,
                const float* __restrict__ bias, float* __restrict__ outf,
                __half* __restrict__ hh, __half* __restrict__ hl,
                int n_nodes, int do_relu) {
    extern __shared__ __align__(1024) char sm[];
    const uint32_t smb = smem_u32(sm);
    const int tid  = threadIdx.x;
    const int lane = tid & 31;
    const int wid  = tid >> 5;
    const int wm   = wid & 3;
    const int wn   = wid >> 2;
    const int row0 = blockIdx.x * 128;

    // staging assignments
    const int pA    = tid >> 8;            // A plane 0=hi,1=lo
    const int rowA  = (tid & 255) >> 1;    // 0..127
    const int halfA = tid & 1;             // 16B half of 32B row
    const int nB    = tid & 255;           // B row (n)
    const int pB    = tid >> 8;            // B plane
    const uint32_t aDst = pA * 6144u + rowA * 48u + halfA * 16u;
    const uint32_t bDst = 12288u + pB * 12288u + nB * 48u;
    const __half* srcB = pB ? g_Btl : g_Bth;

    // ldmatrix lane addressing (48B rows)
    const uint32_t aOff = (uint32_t)(wm * 32 + (lane & 7) + 8 * ((lane >> 3) & 1)) * 48
                        + (((uint32_t)lane >> 4) << 4);
    const uint32_t bOff = (uint32_t)(wn * 64 + ((lane >> 4) << 3) + (lane & 7)) * 48
                        + ((((uint32_t)lane >> 3) & 1) << 4);

    float c[2][8][4];
    #pragma unroll
    for (int t = 0; t < 2; t++)
        #pragma unroll
        for (int nt = 0; nt < 8; nt++)
            #pragma unroll
            for (int j = 0; j < 4; j++) c[t][nt][j] = 0.f;

    uint4 ra, rb0, rb1;
    auto ldg = [&](int s) {
        const __half* srcA = (s < 16) ? (pA ? g_AGl : g_AGh)
                                      : (pA ? inl  : inh);
        const int ss = s & 15;
        ra  = *(const uint4*)(srcA + ((size_t)ss * NPAD + row0 + rowA) * 16
                              + halfA * 8);
        const __half* pb = srcB + s * 4096 + nB * 16;
        rb0 = *(const uint4*)(pb);
        rb1 = *(const uint4*)(pb + 8);
    };
    auto sts = [&](int buf) {
        char* bb = sm + buf * STAGE_B;
        *(uint4*)(bb + aDst)      = ra;
        *(uint4*)(bb + bDst)      = rb0;
        *(uint4*)(bb + bDst + 16) = rb1;
    };
    auto compute = [&](int buf) {
        const uint32_t bb = smb + buf * STAGE_B;
        uint32_t ah[2][4], al[2][4];
        LDSM4(ah[0], bb + aOff);
        LDSM4(ah[1], bb + aOff + 768);
        LDSM4(al[0], bb + 6144 + aOff);
        LDSM4(al[1], bb + 6144 + aOff + 768);
        #pragma unroll
        for (int nt2 = 0; nt2 < 4; nt2++) {
            uint32_t bh[4], bl[4];
            LDSM4(bh, bb + 12288 + bOff + nt2 * 768);
            LDSM4(bl, bb + 24576 + bOff + nt2 * 768);
            #pragma unroll
            for (int t = 0; t < 2; t++) {
                MMA16(c[t][nt2 * 2],     ah[t], bh[0], bh[1]);
                MMA16(c[t][nt2 * 2],     al[t], bh[0], bh[1]);
                MMA16(c[t][nt2 * 2],     ah[t], bl[0], bl[1]);
                MMA16(c[t][nt2 * 2 + 1], ah[t], bh[2], bh[3]);
                MMA16(c[t][nt2 * 2 + 1], al[t], bh[2], bh[3]);
                MMA16(c[t][nt2 * 2 + 1], ah[t], bl[2], bl[3]);
            }
        }
    };

    // prologue
    ldg(0);
    sts(0);
    ldg(1);
    __syncthreads();

    #pragma unroll 1
    for (int s = 0; s < 32; s++) {
        compute(s & 1);
        if (s + 1 < 32) {
            sts((s + 1) & 1);          // write buffer not being read
            if (s + 2 < 32) ldg(s + 2);
        }
        __syncthreads();
    }

    // ---- epilogue ----
    #pragma unroll
    for (int t = 0; t < 2; t++) {
        const int r1 = row0 + wm * 32 + t * 16 + (lane >> 2);
        #pragma unroll
        for (int nt = 0; nt < 8; nt++) {
            const int col = wn * 64 + nt * 8 + 2 * (lane & 3);
            float2 b2 = *(const float2*)(bias + col);
            float v0 = c[t][nt][0] + b2.x;
            float v1 = c[t][nt][1] + b2.y;
            float v2 = c[t][nt][2] + b2.x;
            float v3 = c[t][nt][3] + b2.y;
            if (do_relu) {
                v0 = fmaxf(v0, 0.f); v1 = fmaxf(v1, 0.f);
                v2 = fmaxf(v2, 0.f); v3 = fmaxf(v3, 0.f);
            }
            const int sp = col >> 4, kk = col & 15;
            if (r1 < n_nodes) {
                *(float2*)(outf + (size_t)r1 * D + col) = make_float2(v0, v1);
                if (hh) {
                    size_t off = ((size_t)sp * NPAD + r1) * 16 + kk;
                    __half a, b, la, lb;
                    split2(v0, a, la); split2(v1, b, lb);
                    *(uint32_t*)(hh + off) =
                        (uint32_t)__half_as_ushort(a) |
                        ((uint32_t)__half_as_ushort(b) << 16);
                    *(uint32_t*)(hl + off) =
                        (uint32_t)__half_as_ushort(la) |
                        ((uint32_t)__half_as_ushort(lb) << 16);
                }
            }
            if (r1 + 8 < n_nodes) {
                *(float2*)(outf + (size_t)(r1 + 8) * D + col) = make_float2(v2, v3);
                if (hh) {
                    size_t off = ((size_t)sp * NPAD + r1 + 8) * 16 + kk;
                    __half a, b, la, lb;
                    split2(v2, a, la); split2(v3, b, lb);
                    *(uint32_t*)(hh + off) =
                        (uint32_t)__half_as_ushort(a) |
                        ((uint32_t)__half_as_ushort(b) << 16);
                    *(uint32_t*)(hl + off) =
                        (uint32_t)__half_as_ushort(la) |
                        ((uint32_t)__half_as_ushort(lb) << 16);
                }
            }
        }
    }
}

// ---------------- launch ----------------
extern "C" void kernel_launch(void* const* d_in, const int* in_sizes, int n_in,
                              void* d_out, int out_size) {
    const float* x   = (const float*)d_in[0];
    const int*   raw = (const int*)d_in[1];
    const float* W1l = (const float*)d_in[2];
    const float* b1  = (const float*)d_in[3];
    const float* W1r = (const float*)d_in[4];
    const float* W2l = (const float*)d_in[5];
    const float* b2  = (const float*)d_in[6];
    const float* W2r = (const float*)d_in[7];
    float* out = (float*)d_out;

    const int n_nodes = in_sizes[0] / D;
    const int n_edges = in_sizes[1] / 2;

    float*  hptr;  cudaGetSymbolAddress((void**)&hptr,  g_h);
    __half* xh;    cudaGetSymbolAddress((void**)&xh,    g_Xh);
    __half* xl;    cudaGetSymbolAddress((void**)&xl,    g_Xl);
    __half* hhp;   cudaGetSymbolAddress((void**)&hhp,   g_Hh);
    __half* hlp;   cudaGetSymbolAddress((void**)&hlp,   g_Hl);

    cudaFuncSetAttribute(sage_mma_kernel,
                         cudaFuncAttributeMaxDynamicSharedMemorySize,
                         2 * STAGE_B);

    const int mma_blocks = (n_nodes + 127) / 128;
    const int agg_blocks = (n_nodes * 32 + 255) / 256;
    const int eb = (n_edges + 255) / 256;
    const int nb = (n_nodes + 255) / 256;
    const int wb = (256 * 512 + 255) / 256;
    const int cb = (n_nodes * 64 + 255) / 256;
    const int smem = 2 * STAGE_B;

    // ---- edge dtype detect + decode ----
    zero_flag_kernel<<<1, 1>>>();
    detect_kernel<<<eb, 256>>>(raw, n_edges);
    extract_kernel<<<eb, 256>>>(raw, n_edges, n_nodes);

    // ---- CSR build (reused by both layers) ----
    zero_cnt_kernel<<<nb, 256>>>(n_nodes);
    count_kernel<<<eb, 256>>>(n_edges);
    scan_kernel<<<1, 1024>>>(n_nodes);
    build_kernel<<<eb, 256>>>(n_edges);

    // ---- one-time x plane conversion ----
    convert_x_kernel<<<cb, 256>>>(x, n_nodes);

    // ---- layer 1 ----
    aggregate_kernel<<<agg_blocks, 256>>>(x, n_nodes);
    prep_w_kernel<<<wb, 256>>>(W1l, W1r);
    sage_mma_kernel<<<mma_blocks, 512, smem>>>(xh, xl, b1, hptr, hhp, hlp,
                                               n_nodes, 1);

    // ---- layer 2 ----
    aggregate_kernel<<<agg_blocks, 256>>>(hptr, n_nodes);
    prep_w_kernel<<<wb, 256>>>(W2l, W2r);
    sage_mma_kernel<<<mma_blocks, 512, smem>>>(hhp, hlp, b2, out, nullptr,
                                               nullptr, n_nodes, 0);
}

// round 11
// speedup vs baseline: 1.9570x; 1.0989x over previous
#include <cuda_runtime.h>
#include <cuda_fp16.h>
#include <cstdint>

#define D     256
#define MAXN  50000
#define NPAD  50048
#define MAXE  800000

// ---------------- scratch (no allocations allowed) ----------------
__device__ __align__(16) __half g_Bth[256 * 512];        // B hi, staged [s][n][16]
__device__ __align__(16) __half g_Btl[256 * 512];        // B lo
// A-half fp16 planes, staged [s<16][row][16] (dense, NPAD rows)
__device__ __align__(16) __half g_AGh[(size_t)16 * NPAD * 16];  // agg hi
__device__ __align__(16) __half g_AGl[(size_t)16 * NPAD * 16];  // agg lo
__device__ __align__(16) __half g_Xh [(size_t)16 * NPAD * 16];  // x hi
__device__ __align__(16) __half g_Xl [(size_t)16 * NPAD * 16];  // x lo
__device__ __align__(16) __half g_Hh [(size_t)16 * NPAD * 16];  // h hi
__device__ __align__(16) __half g_Hl [(size_t)16 * NPAD * 16];  // h lo
// fp16 row-major feature copies for the gather (512B/row)
__device__ __align__(16) __half g_X16[(size_t)MAXN * D];
__device__ __align__(16) __half g_H16[(size_t)MAXN * D];
__device__ int g_cnt[MAXN];
__device__ int g_off[MAXN];
__device__ int g_pos[MAXN];
__device__ int g_csr_src[MAXE];
__device__ int g_src[MAXE];
__device__ int g_tgt[MAXE];
__device__ int g_flag;            // 0 => edge dtype int64, nonzero => int32

__device__ __forceinline__ uint32_t smem_u32(const void* p) {
    uint32_t a;
    asm("{ .reg .u64 t; cvta.to.shared.u64 t, %1; cvt.u32.u64 %0, t; }"
        : "=r"(a) : "l"(p));
    return a;
}
__device__ __forceinline__ void split2(float v, __half& h, __half& l) {
    h = __float2half_rn(v);
    l = __float2half_rn(v - __half2float(h));
}
__device__ __forceinline__ uint2 pack4(__half a, __half b, __half c, __half d) {
    uint2 r;
    r.x = (uint32_t)__half_as_ushort(a) | ((uint32_t)__half_as_ushort(b) << 16);
    r.y = (uint32_t)__half_as_ushort(c) | ((uint32_t)__half_as_ushort(d) << 16);
    return r;
}
__device__ __forceinline__ uint4 pack8(const __half* h) {
    uint4 r;
    r.x = (uint32_t)__half_as_ushort(h[0]) | ((uint32_t)__half_as_ushort(h[1]) << 16);
    r.y = (uint32_t)__half_as_ushort(h[2]) | ((uint32_t)__half_as_ushort(h[3]) << 16);
    r.z = (uint32_t)__half_as_ushort(h[4]) | ((uint32_t)__half_as_ushort(h[5]) << 16);
    r.w = (uint32_t)__half_as_ushort(h[6]) | ((uint32_t)__half_as_ushort(h[7]) << 16);
    return r;
}
__device__ __forceinline__ void add8(float* a, uint4 v) {
    float2 f;
    f = __half22float2(*(__half2*)&v.x); a[0] += f.x; a[1] += f.y;
    f = __half22float2(*(__half2*)&v.y); a[2] += f.x; a[3] += f.y;
    f = __half22float2(*(__half2*)&v.z); a[4] += f.x; a[5] += f.y;
    f = __half22float2(*(__half2*)&v.w); a[6] += f.x; a[7] += f.y;
}

// ---------------- init: zero counts + flag ----------------
__global__ void zero_init_kernel(int n) {
    int i = blockIdx.x * blockDim.x + threadIdx.x;
    if (i < n) g_cnt[i] = 0;
    if (i == 0) g_flag = 0;
}

// ---------------- edge dtype detect ----------------
__global__ void detect_kernel(const int* __restrict__ raw, int n_edges) {
    int i = blockIdx.x * blockDim.x + threadIdx.x;
    if (i < n_edges) {
        if (raw[2 * i + 1] != 0) atomicOr(&g_flag, 1);
    }
}

// ---------------- decode + in-degree count (fused) ----------------
__global__ void extract_count_kernel(const int* __restrict__ raw,
                                     int n_edges, int n_nodes) {
    int e = blockIdx.x * blockDim.x + threadIdx.x;
    if (e >= n_edges) return;
    int s, t;
    if (g_flag == 0) {             // int64 layout: low word of each int64
        s = raw[2 * e];
        t = raw[2 * (n_edges + e)];
    } else {                       // int32 layout
        s = raw[e];
        t = raw[n_edges + e];
    }
    s = min(max(s, 0), n_nodes - 1);
    t = min(max(t, 0), n_nodes - 1);
    g_src[e] = s;
    g_tgt[e] = t;
    atomicAdd(&g_cnt[t], 1);
}

// ---------------- single-block scan of g_cnt -> g_off, g_pos ----------------
__global__ void scan_kernel(int n) {
    const int T = 1024;
    __shared__ int sh[T];
    int tid = threadIdx.x;
    int chunk = (n + T - 1) / T;
    int start = tid * chunk;
    int end   = min(start + chunk, n);

    int sum = 0;
    for (int i = start; i < end; i++) sum += g_cnt[i];
    sh[tid] = sum;
    __syncthreads();

    for (int off = 1; off < T; off <<= 1) {
        int v = (tid >= off) ? sh[tid - off] : 0;
        __syncthreads();
        sh[tid] += v;
        __syncthreads();
    }
    int run = (tid == 0) ? 0 : sh[tid - 1];
    for (int i = start; i < end; i++) {
        g_off[i] = run;
        g_pos[i] = run;
        run += g_cnt[i];
    }
}

__global__ void build_kernel(int n_edges) {
    int e = blockIdx.x * blockDim.x + threadIdx.x;
    if (e < n_edges) {
        int p = atomicAdd(&g_pos[g_tgt[e]], 1);
        g_csr_src[p] = g_src[e];
    }
}

// ---------------- one-time x -> fp16 row copy + staged hi/lo planes --------
__global__ void convert_x_kernel(const float* __restrict__ x, int n_nodes) {
    int t = blockIdx.x * blockDim.x + threadIdx.x;
    if (t >= n_nodes * 64) return;
    int row = t >> 6;
    int g   = t & 63;                  // k0 = 4g
    float4 v = *(const float4*)(x + (size_t)row * D + g * 4);
    __half h0, l0, h1, l1, h2, l2, h3, l3;
    split2(v.x, h0, l0); split2(v.y, h1, l1);
    split2(v.z, h2, l2); split2(v.w, h3, l3);
    size_t off = ((size_t)(g >> 2) * NPAD + row) * 16 + (g & 3) * 4;
    *(uint2*)(g_Xh + off) = pack4(h0, h1, h2, h3);
    *(uint2*)(g_Xl + off) = pack4(l0, l1, l2, l3);
    *(uint2*)(g_X16 + (size_t)row * D + g * 4) = pack4(h0, h1, h2, h3);
}

// ---------------- gather mean-aggregate over fp16 rows (512B/row) ----------
// one warp per node; lane covers k = 8*lane .. 8*lane+7; writes staged planes
__global__ void __launch_bounds__(256)
aggregate16_kernel(const __half* __restrict__ feat, int n_nodes,
                   __half* __restrict__ outh, __half* __restrict__ outl) {
    int warp = (blockIdx.x * blockDim.x + threadIdx.x) >> 5;
    int lane = threadIdx.x & 31;
    if (warp >= n_nodes) return;

    int beg = g_off[warp];
    int deg = g_cnt[warp];

    float acc[8] = {0.f, 0.f, 0.f, 0.f, 0.f, 0.f, 0.f, 0.f};
    int i = 0;
    for (; i + 4 <= deg; i += 4) {
        int s0 = __ldg(&g_csr_src[beg + i]);
        int s1 = __ldg(&g_csr_src[beg + i + 1]);
        int s2 = __ldg(&g_csr_src[beg + i + 2]);
        int s3 = __ldg(&g_csr_src[beg + i + 3]);
        uint4 v0 = *(const uint4*)(feat + (size_t)s0 * D + lane * 8);
        uint4 v1 = *(const uint4*)(feat + (size_t)s1 * D + lane * 8);
        uint4 v2 = *(const uint4*)(feat + (size_t)s2 * D + lane * 8);
        uint4 v3 = *(const uint4*)(feat + (size_t)s3 * D + lane * 8);
        add8(acc, v0); add8(acc, v1); add8(acc, v2); add8(acc, v3);
    }
    for (; i < deg; i++) {
        int s0 = __ldg(&g_csr_src[beg + i]);
        uint4 v0 = *(const uint4*)(feat + (size_t)s0 * D + lane * 8);
        add8(acc, v0);
    }

    float iv = 1.0f / (float)(deg > 1 ? deg : 1);
    __half h[8], l[8];
    #pragma unroll
    for (int j = 0; j < 8; j++) split2(acc[j] * iv, h[j], l[j]);

    const int sp = lane >> 1;
    const int kk = (lane & 1) * 8;
    size_t off = ((size_t)sp * NPAD + warp) * 16 + kk;
    *(uint4*)(outh + off) = pack8(h);
    *(uint4*)(outl + off) = pack8(l);
}

// ---------------- W prep: [Wl;Wr]^T -> fp16 hi/lo, staged [s][n][16] -------
__global__ void prep_w_kernel(const float* __restrict__ Wl,
                              const float* __restrict__ Wr) {
    int tid = blockIdx.x * blockDim.x + threadIdx.x;
    if (tid >= 256 * 512) return;
    int k = tid & 511;
    int n = tid >> 9;
    float v = (k < 256) ? Wl[(size_t)k * 256 + n]
                        : Wr[(size_t)(k - 256) * 256 + n];
    __half h, l;
    split2(v, h, l);
    int off = (k >> 4) * 4096 + n * 16 + (k & 15);
    g_Bth[off] = h;
    g_Btl[off] = l;
}

// ---------------- mma.sync fp16-split GEMM (3 passes, fp32 accum) ----------
// CTA 128x256, K=512, 32 stages BK=16, 512 thr = 16 warps (4x4), warp 32x64.
#define STAGE_B 36864

#define LDSM4(r, addr)                                                      \
    asm volatile("ldmatrix.sync.aligned.m8n8.x4.shared.b16 "                \
                 "{%0,%1,%2,%3}, [%4];"                                     \
                 : "=r"((r)[0]), "=r"((r)[1]), "=r"((r)[2]), "=r"((r)[3])   \
                 : "r"(addr))

#define MMA16(cc, a, b0, b1)                                                \
    asm volatile("mma.sync.aligned.m16n8k16.row.col.f32.f16.f16.f32 "       \
                 "{%0,%1,%2,%3},{%4,%5,%6,%7},{%8,%9},{%0,%1,%2,%3};"       \
                 : "+f"((cc)[0]), "+f"((cc)[1]), "+f"((cc)[2]), "+f"((cc)[3]) \
                 : "r"((a)[0]), "r"((a)[1]), "r"((a)[2]), "r"((a)[3]),      \
                   "r"(b0), "r"(b1))

__global__ void __launch_bounds__(512, 1)
sage_mma_kernel(const __half* __restrict__ inh, const __half* __restrict__ inl,
                const float* __restrict__ bias, float* __restrict__ outf,
                __half* __restrict__ hh, __half* __restrict__ hl,
                __half* __restrict__ h16,
                int n_nodes, int do_relu) {
    extern __shared__ __align__(1024) char sm[];
    const uint32_t smb = smem_u32(sm);
    const int tid  = threadIdx.x;
    const int lane = tid & 31;
    const int wid  = tid >> 5;
    const int wm   = wid & 3;
    const int wn   = wid >> 2;
    const int row0 = blockIdx.x * 128;

    // staging assignments
    const int pA    = tid >> 8;            // A plane 0=hi,1=lo
    const int rowA  = (tid & 255) >> 1;    // 0..127
    const int halfA = tid & 1;             // 16B half of 32B row
    const int nB    = tid & 255;           // B row (n)
    const int pB    = tid >> 8;            // B plane
    const uint32_t aDst = pA * 6144u + rowA * 48u + halfA * 16u;
    const uint32_t bDst = 12288u + pB * 12288u + nB * 48u;
    const __half* srcB = pB ? g_Btl : g_Bth;

    // ldmatrix lane addressing (48B rows)
    const uint32_t aOff = (uint32_t)(wm * 32 + (lane & 7) + 8 * ((lane >> 3) & 1)) * 48
                        + (((uint32_t)lane >> 4) << 4);
    const uint32_t bOff = (uint32_t)(wn * 64 + ((lane >> 4) << 3) + (lane & 7)) * 48
                        + ((((uint32_t)lane >> 3) & 1) << 4);

    float c[2][8][4];
    #pragma unroll
    for (int t = 0; t < 2; t++)
        #pragma unroll
        for (int nt = 0; nt < 8; nt++)
            #pragma unroll
            for (int j = 0; j < 4; j++) c[t][nt][j] = 0.f;

    uint4 ra, rb0, rb1;
    auto ldg = [&](int s) {
        const __half* srcA = (s < 16) ? (pA ? g_AGl : g_AGh)
                                      : (pA ? inl  : inh);
        const int ss = s & 15;
        ra  = *(const uint4*)(srcA + ((size_t)ss * NPAD + row0 + rowA) * 16
                              + halfA * 8);
        const __half* pb = srcB + s * 4096 + nB * 16;
        rb0 = *(const uint4*)(pb);
        rb1 = *(const uint4*)(pb + 8);
    };
    auto sts = [&](int buf) {
        char* bb = sm + buf * STAGE_B;
        *(uint4*)(bb + aDst)      = ra;
        *(uint4*)(bb + bDst)      = rb0;
        *(uint4*)(bb + bDst + 16) = rb1;
    };
    auto compute = [&](int buf) {
        const uint32_t bb = smb + buf * STAGE_B;
        uint32_t ah[2][4], al[2][4];
        LDSM4(ah[0], bb + aOff);
        LDSM4(ah[1], bb + aOff + 768);
        LDSM4(al[0], bb + 6144 + aOff);
        LDSM4(al[1], bb + 6144 + aOff + 768);
        #pragma unroll
        for (int nt2 = 0; nt2 < 4; nt2++) {
            uint32_t bh[4], bl[4];
            LDSM4(bh, bb + 12288 + bOff + nt2 * 768);
            LDSM4(bl, bb + 24576 + bOff + nt2 * 768);
            #pragma unroll
            for (int t = 0; t < 2; t++) {
                MMA16(c[t][nt2 * 2],     ah[t], bh[0], bh[1]);
                MMA16(c[t][nt2 * 2],     al[t], bh[0], bh[1]);
                MMA16(c[t][nt2 * 2],     ah[t], bl[0], bl[1]);
                MMA16(c[t][nt2 * 2 + 1], ah[t], bh[2], bh[3]);
                MMA16(c[t][nt2 * 2 + 1], al[t], bh[2], bh[3]);
                MMA16(c[t][nt2 * 2 + 1], ah[t], bl[2], bl[3]);
            }
        }
    };

    // prologue
    ldg(0);
    sts(0);
    ldg(1);
    __syncthreads();

    #pragma unroll 1
    for (int s = 0; s < 32; s++) {
        compute(s & 1);
        if (s + 1 < 32) {
            sts((s + 1) & 1);          // write buffer not being read
            if (s + 2 < 32) ldg(s + 2);
        }
        __syncthreads();
    }

    // ---- epilogue ----
    #pragma unroll
    for (int t = 0; t < 2; t++) {
        const int r1 = row0 + wm * 32 + t * 16 + (lane >> 2);
        #pragma unroll
        for (int nt = 0; nt < 8; nt++) {
            const int col = wn * 64 + nt * 8 + 2 * (lane & 3);
            float2 b2 = *(const float2*)(bias + col);
            float v0 = c[t][nt][0] + b2.x;
            float v1 = c[t][nt][1] + b2.y;
            float v2 = c[t][nt][2] + b2.x;
            float v3 = c[t][nt][3] + b2.y;
            if (do_relu) {
                v0 = fmaxf(v0, 0.f); v1 = fmaxf(v1, 0.f);
                v2 = fmaxf(v2, 0.f); v3 = fmaxf(v3, 0.f);
            }
            const int sp = col >> 4, kk = col & 15;
            if (r1 < n_nodes) {
                if (outf)
                    *(float2*)(outf + (size_t)r1 * D + col) = make_float2(v0, v1);
                if (hh) {
                    size_t off = ((size_t)sp * NPAD + r1) * 16 + kk;
                    __half a, b, la, lb;
                    split2(v0, a, la); split2(v1, b, lb);
                    uint32_t hi2 = (uint32_t)__half_as_ushort(a) |
                                   ((uint32_t)__half_as_ushort(b) << 16);
                    *(uint32_t*)(hh + off) = hi2;
                    *(uint32_t*)(hl + off) =
                        (uint32_t)__half_as_ushort(la) |
                        ((uint32_t)__half_as_ushort(lb) << 16);
                    *(uint32_t*)(h16 + (size_t)r1 * D + col) = hi2;
                }
            }
            if (r1 + 8 < n_nodes) {
                if (outf)
                    *(float2*)(outf + (size_t)(r1 + 8) * D + col) = make_float2(v2, v3);
                if (hh) {
                    size_t off = ((size_t)sp * NPAD + r1 + 8) * 16 + kk;
                    __half a, b, la, lb;
                    split2(v2, a, la); split2(v3, b, lb);
                    uint32_t hi2 = (uint32_t)__half_as_ushort(a) |
                                   ((uint32_t)__half_as_ushort(b) << 16);
                    *(uint32_t*)(hh + off) = hi2;
                    *(uint32_t*)(hl + off) =
                        (uint32_t)__half_as_ushort(la) |
                        ((uint32_t)__half_as_ushort(lb) << 16);
                    *(uint32_t*)(h16 + (size_t)(r1 + 8) * D + col) = hi2;
                }
            }
        }
    }
}

// ---------------- launch ----------------
extern "C" void kernel_launch(void* const* d_in, const int* in_sizes, int n_in,
                              void* d_out, int out_size) {
    const float* x   = (const float*)d_in[0];
    const int*   raw = (const int*)d_in[1];
    const float* W1l = (const float*)d_in[2];
    const float* b1  = (const float*)d_in[3];
    const float* W1r = (const float*)d_in[4];
    const float* W2l = (const float*)d_in[5];
    const float* b2  = (const float*)d_in[6];
    const float* W2r = (const float*)d_in[7];
    float* out = (float*)d_out;

    const int n_nodes = in_sizes[0] / D;
    const int n_edges = in_sizes[1] / 2;

    __half *xh, *xl, *hhp, *hlp, *agh, *agl, *x16, *h16;
    cudaGetSymbolAddress((void**)&xh,  g_Xh);
    cudaGetSymbolAddress((void**)&xl,  g_Xl);
    cudaGetSymbolAddress((void**)&hhp, g_Hh);
    cudaGetSymbolAddress((void**)&hlp, g_Hl);
    cudaGetSymbolAddress((void**)&agh, g_AGh);
    cudaGetSymbolAddress((void**)&agl, g_AGl);
    cudaGetSymbolAddress((void**)&x16, g_X16);
    cudaGetSymbolAddress((void**)&h16, g_H16);

    cudaFuncSetAttribute(sage_mma_kernel,
                         cudaFuncAttributeMaxDynamicSharedMemorySize,
                         2 * STAGE_B);

    const int mma_blocks = (n_nodes + 127) / 128;
    const int agg_blocks = (n_nodes * 32 + 255) / 256;
    const int eb = (n_edges + 255) / 256;
    const int nb = (n_nodes + 255) / 256;
    const int wb = (256 * 512 + 255) / 256;
    const int cb = (n_nodes * 64 + 255) / 256;
    const int smem = 2 * STAGE_B;

    // ---- decode + CSR build ----
    zero_init_kernel<<<nb, 256>>>(n_nodes);
    detect_kernel<<<eb, 256>>>(raw, n_edges);
    extract_count_kernel<<<eb, 256>>>(raw, n_edges, n_nodes);
    scan_kernel<<<1, 1024>>>(n_nodes);
    build_kernel<<<eb, 256>>>(n_edges);

    // ---- one-time x conversion (fp16 row copy + staged planes) ----
    convert_x_kernel<<<cb, 256>>>(x, n_nodes);

    // ---- layer 1 ----
    aggregate16_kernel<<<agg_blocks, 256>>>(x16, n_nodes, agh, agl);
    prep_w_kernel<<<wb, 256>>>(W1l, W1r);
    sage_mma_kernel<<<mma_blocks, 512, smem>>>(xh, xl, b1, nullptr,
                                               hhp, hlp, h16, n_nodes, 1);

    // ---- layer 2 ----
    aggregate16_kernel<<<agg_blocks, 256>>>(h16, n_nodes, agh, agl);
    prep_w_kernel<<<wb, 256>>>(W2l, W2r);
    sage_mma_kernel<<<mma_blocks, 512, smem>>>(hhp, hlp, b2, out,
                                               nullptr, nullptr, nullptr,
                                               n_nodes, 0);
}

// round 12
// speedup vs baseline: 2.7330x; 1.3966x over previous
#include <cuda_runtime.h>
#include <cuda_fp16.h>
#include <cstdint>

#define D     256
#define MAXN  50000
#define NPAD  50048
#define MAXE  800000

// ---------------- scratch (no allocations allowed) ----------------
__device__ __align__(16) __half g_Bth[256 * 512];        // B hi, staged [s][n][16]
// A-half fp16 planes, staged [s<16][row][16] (dense, NPAD rows)
__device__ __align__(16) __half g_AGh[(size_t)16 * NPAD * 16];  // agg hi
__device__ __align__(16) __half g_AGl[(size_t)16 * NPAD * 16];  // agg lo
__device__ __align__(16) __half g_Xh [(size_t)16 * NPAD * 16];  // x hi
__device__ __align__(16) __half g_Xl [(size_t)16 * NPAD * 16];  // x lo
__device__ __align__(16) __half g_Hh [(size_t)16 * NPAD * 16];  // h hi
__device__ __align__(16) __half g_Hl [(size_t)16 * NPAD * 16];  // h lo
// fp16 row-major feature copies for the gather (512B/row)
__device__ __align__(16) __half g_X16[(size_t)MAXN * D];
__device__ __align__(16) __half g_H16[(size_t)MAXN * D];
__device__ int g_cnt[MAXN];
__device__ int g_off[MAXN];
__device__ int g_pos[MAXN];
__device__ int g_bsum[256];       // per-block scan partials
__device__ int g_csr_src[MAXE];
__device__ int g_src[MAXE];
__device__ int g_tgt[MAXE];
__device__ int g_flag;            // 0 => edge dtype int64, nonzero => int32

__device__ __forceinline__ uint32_t smem_u32(const void* p) {
    uint32_t a;
    asm("{ .reg .u64 t; cvta.to.shared.u64 t, %1; cvt.u32.u64 %0, t; }"
        : "=r"(a) : "l"(p));
    return a;
}
__device__ __forceinline__ void split2(float v, __half& h, __half& l) {
    h = __float2half_rn(v);
    l = __float2half_rn(v - __half2float(h));
}
__device__ __forceinline__ uint2 pack4(__half a, __half b, __half c, __half d) {
    uint2 r;
    r.x = (uint32_t)__half_as_ushort(a) | ((uint32_t)__half_as_ushort(b) << 16);
    r.y = (uint32_t)__half_as_ushort(c) | ((uint32_t)__half_as_ushort(d) << 16);
    return r;
}
__device__ __forceinline__ uint4 pack8(const __half* h) {
    uint4 r;
    r.x = (uint32_t)__half_as_ushort(h[0]) | ((uint32_t)__half_as_ushort(h[1]) << 16);
    r.y = (uint32_t)__half_as_ushort(h[2]) | ((uint32_t)__half_as_ushort(h[3]) << 16);
    r.z = (uint32_t)__half_as_ushort(h[4]) | ((uint32_t)__half_as_ushort(h[5]) << 16);
    r.w = (uint32_t)__half_as_ushort(h[6]) | ((uint32_t)__half_as_ushort(h[7]) << 16);
    return r;
}
__device__ __forceinline__ void add8(float* a, uint4 v) {
    float2 f;
    f = __half22float2(*(__half2*)&v.x); a[0] += f.x; a[1] += f.y;
    f = __half22float2(*(__half2*)&v.y); a[2] += f.x; a[3] += f.y;
    f = __half22float2(*(__half2*)&v.z); a[4] += f.x; a[5] += f.y;
    f = __half22float2(*(__half2*)&v.w); a[6] += f.x; a[7] += f.y;
}

// ---------------- init: zero counts + flag ----------------
__global__ void zero_init_kernel(int n) {
    int i = blockIdx.x * blockDim.x + threadIdx.x;
    if (i < n) g_cnt[i] = 0;
    if (i == 0) g_flag = 0;
}

// ---------------- edge dtype detect ----------------
__global__ void detect_kernel(const int* __restrict__ raw, int n_edges) {
    int i = blockIdx.x * blockDim.x + threadIdx.x;
    if (i < n_edges) {
        if (raw[2 * i + 1] != 0) atomicOr(&g_flag, 1);
    }
}

// ---------------- decode + in-degree count (fused) ----------------
__global__ void extract_count_kernel(const int* __restrict__ raw,
                                     int n_edges, int n_nodes) {
    int e = blockIdx.x * blockDim.x + threadIdx.x;
    if (e >= n_edges) return;
    int s, t;
    if (g_flag == 0) {             // int64 layout: low word of each int64
        s = raw[2 * e];
        t = raw[2 * (n_edges + e)];
    } else {                       // int32 layout
        s = raw[e];
        t = raw[n_edges + e];
    }
    s = min(max(s, 0), n_nodes - 1);
    t = min(max(t, 0), n_nodes - 1);
    g_src[e] = s;
    g_tgt[e] = t;
    atomicAdd(&g_cnt[t], 1);
}

// ---------------- parallel 3-phase scan of g_cnt -> g_off, g_pos -----------
// Phase A: 256-wide block inclusive scan; within-block inclusive -> g_pos
__global__ void scan_a_kernel(int n) {
    __shared__ int sh[256];
    int tid = threadIdx.x;
    int i = blockIdx.x * 256 + tid;
    int v = (i < n) ? g_cnt[i] : 0;
    sh[tid] = v;
    __syncthreads();
    #pragma unroll
    for (int off = 1; off < 256; off <<= 1) {
        int t = (tid >= off) ? sh[tid - off] : 0;
        __syncthreads();
        sh[tid] += t;
        __syncthreads();
    }
    if (i < n) g_pos[i] = sh[tid];
    if (tid == 255) g_bsum[blockIdx.x] = sh[255];
}
// Phase B: single block scans the per-block totals (inclusive)
__global__ void scan_b_kernel(int nb) {
    __shared__ int sh[256];
    int tid = threadIdx.x;
    sh[tid] = (tid < nb) ? g_bsum[tid] : 0;
    __syncthreads();
    #pragma unroll
    for (int off = 1; off < 256; off <<= 1) {
        int t = (tid >= off) ? sh[tid - off] : 0;
        __syncthreads();
        sh[tid] += t;
        __syncthreads();
    }
    if (tid < nb) g_bsum[tid] = sh[tid];
}
// Phase C: exclusive offset = block_base + (incl_within_block - cnt)
__global__ void scan_c_kernel(int n) {
    int i = blockIdx.x * 256 + threadIdx.x;
    if (i >= n) return;
    int base = blockIdx.x ? g_bsum[blockIdx.x - 1] : 0;
    int off = base + g_pos[i] - g_cnt[i];
    g_off[i] = off;
    g_pos[i] = off;
}

__global__ void build_kernel(int n_edges) {
    int e = blockIdx.x * blockDim.x + threadIdx.x;
    if (e < n_edges) {
        int p = atomicAdd(&g_pos[g_tgt[e]], 1);
        g_csr_src[p] = g_src[e];
    }
}

// ---------------- one-time x -> fp16 row copy + staged hi/lo planes --------
__global__ void convert_x_kernel(const float* __restrict__ x, int n_nodes) {
    int t = blockIdx.x * blockDim.x + threadIdx.x;
    if (t >= n_nodes * 64) return;
    int row = t >> 6;
    int g   = t & 63;                  // k0 = 4g
    float4 v = *(const float4*)(x + (size_t)row * D + g * 4);
    __half h0, l0, h1, l1, h2, l2, h3, l3;
    split2(v.x, h0, l0); split2(v.y, h1, l1);
    split2(v.z, h2, l2); split2(v.w, h3, l3);
    size_t off = ((size_t)(g >> 2) * NPAD + row) * 16 + (g & 3) * 4;
    *(uint2*)(g_Xh + off) = pack4(h0, h1, h2, h3);
    *(uint2*)(g_Xl + off) = pack4(l0, l1, l2, l3);
    *(uint2*)(g_X16 + (size_t)row * D + g * 4) = pack4(h0, h1, h2, h3);
}

// ---------------- gather mean-aggregate over fp16 rows (512B/row) ----------
__global__ void __launch_bounds__(256)
aggregate16_kernel(const __half* __restrict__ feat, int n_nodes,
                   __half* __restrict__ outh, __half* __restrict__ outl) {
    int warp = (blockIdx.x * blockDim.x + threadIdx.x) >> 5;
    int lane = threadIdx.x & 31;
    if (warp >= n_nodes) return;

    int beg = g_off[warp];
    int deg = g_cnt[warp];

    float acc[8] = {0.f, 0.f, 0.f, 0.f, 0.f, 0.f, 0.f, 0.f};
    int i = 0;
    for (; i + 4 <= deg; i += 4) {
        int s0 = __ldg(&g_csr_src[beg + i]);
        int s1 = __ldg(&g_csr_src[beg + i + 1]);
        int s2 = __ldg(&g_csr_src[beg + i + 2]);
        int s3 = __ldg(&g_csr_src[beg + i + 3]);
        uint4 v0 = *(const uint4*)(feat + (size_t)s0 * D + lane * 8);
        uint4 v1 = *(const uint4*)(feat + (size_t)s1 * D + lane * 8);
        uint4 v2 = *(const uint4*)(feat + (size_t)s2 * D + lane * 8);
        uint4 v3 = *(const uint4*)(feat + (size_t)s3 * D + lane * 8);
        add8(acc, v0); add8(acc, v1); add8(acc, v2); add8(acc, v3);
    }
    for (; i < deg; i++) {
        int s0 = __ldg(&g_csr_src[beg + i]);
        uint4 v0 = *(const uint4*)(feat + (size_t)s0 * D + lane * 8);
        add8(acc, v0);
    }

    float iv = 1.0f / (float)(deg > 1 ? deg : 1);
    __half h[8], l[8];
    #pragma unroll
    for (int j = 0; j < 8; j++) split2(acc[j] * iv, h[j], l[j]);

    const int sp = lane >> 1;
    const int kk = (lane & 1) * 8;
    size_t off = ((size_t)sp * NPAD + warp) * 16 + kk;
    *(uint4*)(outh + off) = pack8(h);
    *(uint4*)(outl + off) = pack8(l);
}

// ---------------- W prep: [Wl;Wr]^T -> fp16 hi, staged [s][n][16] ----------
__global__ void prep_w_kernel(const float* __restrict__ Wl,
                              const float* __restrict__ Wr) {
    int tid = blockIdx.x * blockDim.x + threadIdx.x;
    if (tid >= 256 * 512) return;
    int k = tid & 511;
    int n = tid >> 9;
    float v = (k < 256) ? Wl[(size_t)k * 256 + n]
                        : Wr[(size_t)(k - 256) * 256 + n];
    g_Bth[(k >> 4) * 4096 + n * 16 + (k & 15)] = __float2half_rn(v);
}

// ---------------- mma.sync fp16-split GEMM (2 passes, fp32 accum) ----------
// CTA 128x256, K=512, 32 stages BK=16, 512 thr = 16 warps (4x4), warp 32x64.
// Stage smem: Ah[128][24h] Al Bh[256][24h] = 24576B, x2 buffers.
#define STAGE_B 24576

#define LDSM4(r, addr)                                                      \
    asm volatile("ldmatrix.sync.aligned.m8n8.x4.shared.b16 "                \
                 "{%0,%1,%2,%3}, [%4];"                                     \
                 : "=r"((r)[0]), "=r"((r)[1]), "=r"((r)[2]), "=r"((r)[3])   \
                 : "r"(addr))

#define MMA16(cc, a, b0, b1)                                                \
    asm volatile("mma.sync.aligned.m16n8k16.row.col.f32.f16.f16.f32 "       \
                 "{%0,%1,%2,%3},{%4,%5,%6,%7},{%8,%9},{%0,%1,%2,%3};"       \
                 : "+f"((cc)[0]), "+f"((cc)[1]), "+f"((cc)[2]), "+f"((cc)[3]) \
                 : "r"((a)[0]), "r"((a)[1]), "r"((a)[2]), "r"((a)[3]),      \
                   "r"(b0), "r"(b1))

__global__ void __launch_bounds__(512, 1)
sage_mma_kernel(const __half* __restrict__ inh, const __half* __restrict__ inl,
                const float* __restrict__ bias, float* __restrict__ outf,
                __half* __restrict__ hh, __half* __restrict__ hl,
                __half* __restrict__ h16,
                int n_nodes, int do_relu) {
    extern __shared__ __align__(1024) char sm[];
    const uint32_t smb = smem_u32(sm);
    const int tid  = threadIdx.x;
    const int lane = tid & 31;
    const int wid  = tid >> 5;
    const int wm   = wid & 3;
    const int wn   = wid >> 2;
    const int row0 = blockIdx.x * 128;

    // staging assignments: each thread stages 16B of A and 16B of B
    const int pA    = tid >> 8;            // A plane 0=hi,1=lo
    const int rowA  = (tid & 255) >> 1;    // 0..127
    const int halfA = tid & 1;
    const int nB    = tid >> 1;            // 0..255
    const int halfB = tid & 1;
    const uint32_t aDst = pA * 6144u + rowA * 48u + halfA * 16u;
    const uint32_t bDst = 12288u + nB * 48u + halfB * 16u;

    // ldmatrix lane addressing (48B rows)
    const uint32_t aOff = (uint32_t)(wm * 32 + (lane & 7) + 8 * ((lane >> 3) & 1)) * 48
                        + (((uint32_t)lane >> 4) << 4);
    const uint32_t bOff = (uint32_t)(wn * 64 + ((lane >> 4) << 3) + (lane & 7)) * 48
                        + ((((uint32_t)lane >> 3) & 1) << 4);

    float c[2][8][4];
    #pragma unroll
    for (int t = 0; t < 2; t++)
        #pragma unroll
        for (int nt = 0; nt < 8; nt++)
            #pragma unroll
            for (int j = 0; j < 4; j++) c[t][nt][j] = 0.f;

    uint4 ra, rb;
    auto ldg = [&](int s) {
        const __half* srcA = (s < 16) ? (pA ? g_AGl : g_AGh)
                                      : (pA ? inl  : inh);
        const int ss = s & 15;
        ra = *(const uint4*)(srcA + ((size_t)ss * NPAD + row0 + rowA) * 16
                             + halfA * 8);
        rb = *(const uint4*)(g_Bth + s * 4096 + nB * 16 + halfB * 8);
    };
    auto sts = [&](int buf) {
        char* bb = sm + buf * STAGE_B;
        *(uint4*)(bb + aDst) = ra;
        *(uint4*)(bb + bDst) = rb;
    };
    auto compute = [&](int buf) {
        const uint32_t bb = smb + buf * STAGE_B;
        uint32_t ah[2][4], al[2][4];
        LDSM4(ah[0], bb + aOff);
        LDSM4(ah[1], bb + aOff + 768);
        LDSM4(al[0], bb + 6144 + aOff);
        LDSM4(al[1], bb + 6144 + aOff + 768);
        #pragma unroll
        for (int nt2 = 0; nt2 < 4; nt2++) {
            uint32_t bh[4];
            LDSM4(bh, bb + 12288 + bOff + nt2 * 768);
            #pragma unroll
            for (int t = 0; t < 2; t++) {
                MMA16(c[t][nt2 * 2],     ah[t], bh[0], bh[1]);
                MMA16(c[t][nt2 * 2],     al[t], bh[0], bh[1]);
                MMA16(c[t][nt2 * 2 + 1], ah[t], bh[2], bh[3]);
                MMA16(c[t][nt2 * 2 + 1], al[t], bh[2], bh[3]);
            }
        }
    };

    // prologue
    ldg(0);
    sts(0);
    ldg(1);
    __syncthreads();

    #pragma unroll 1
    for (int s = 0; s < 32; s++) {
        compute(s & 1);
        if (s + 1 < 32) {
            sts((s + 1) & 1);          // write buffer not being read
            if (s + 2 < 32) ldg(s + 2);
        }
        __syncthreads();
    }

    // ---- epilogue ----
    #pragma unroll
    for (int t = 0; t < 2; t++) {
        const int r1 = row0 + wm * 32 + t * 16 + (lane >> 2);
        #pragma unroll
        for (int nt = 0; nt < 8; nt++) {
            const int col = wn * 64 + nt * 8 + 2 * (lane & 3);
            float2 b2 = *(const float2*)(bias + col);
            float v0 = c[t][nt][0] + b2.x;
            float v1 = c[t][nt][1] + b2.y;
            float v2 = c[t][nt][2] + b2.x;
            float v3 = c[t][nt][3] + b2.y;
            if (do_relu) {
                v0 = fmaxf(v0, 0.f); v1 = fmaxf(v1, 0.f);
                v2 = fmaxf(v2, 0.f); v3 = fmaxf(v3, 0.f);
            }
            const int sp = col >> 4, kk = col & 15;
            if (r1 < n_nodes) {
                if (outf)
                    *(float2*)(outf + (size_t)r1 * D + col) = make_float2(v0, v1);
                if (hh) {
                    size_t off = ((size_t)sp * NPAD + r1) * 16 + kk;
                    __half a, b, la, lb;
                    split2(v0, a, la); split2(v1, b, lb);
                    uint32_t hi2 = (uint32_t)__half_as_ushort(a) |
                                   ((uint32_t)__half_as_ushort(b) << 16);
                    *(uint32_t*)(hh + off) = hi2;
                    *(uint32_t*)(hl + off) =
                        (uint32_t)__half_as_ushort(la) |
                        ((uint32_t)__half_as_ushort(lb) << 16);
                    *(uint32_t*)(h16 + (size_t)r1 * D + col) = hi2;
                }
            }
            if (r1 + 8 < n_nodes) {
                if (outf)
                    *(float2*)(outf + (size_t)(r1 + 8) * D + col) = make_float2(v2, v3);
                if (hh) {
                    size_t off = ((size_t)sp * NPAD + r1 + 8) * 16 + kk;
                    __half a, b, la, lb;
                    split2(v2, a, la); split2(v3, b, lb);
                    uint32_t hi2 = (uint32_t)__half_as_ushort(a) |
                                   ((uint32_t)__half_as_ushort(b) << 16);
                    *(uint32_t*)(hh + off) = hi2;
                    *(uint32_t*)(hl + off) =
                        (uint32_t)__half_as_ushort(la) |
                        ((uint32_t)__half_as_ushort(lb) << 16);
                    *(uint32_t*)(h16 + (size_t)(r1 + 8) * D + col) = hi2;
                }
            }
        }
    }
}

// ---------------- launch ----------------
extern "C" void kernel_launch(void* const* d_in, const int* in_sizes, int n_in,
                              void* d_out, int out_size) {
    const float* x   = (const float*)d_in[0];
    const int*   raw = (const int*)d_in[1];
    const float* W1l = (const float*)d_in[2];
    const float* b1  = (const float*)d_in[3];
    const float* W1r = (const float*)d_in[4];
    const float* W2l = (const float*)d_in[5];
    const float* b2  = (const float*)d_in[6];
    const float* W2r = (const float*)d_in[7];
    float* out = (float*)d_out;

    const int n_nodes = in_sizes[0] / D;
    const int n_edges = in_sizes[1] / 2;

    __half *xh, *xl, *hhp, *hlp, *agh, *agl, *x16, *h16;
    cudaGetSymbolAddress((void**)&xh,  g_Xh);
    cudaGetSymbolAddress((void**)&xl,  g_Xl);
    cudaGetSymbolAddress((void**)&hhp, g_Hh);
    cudaGetSymbolAddress((void**)&hlp, g_Hl);
    cudaGetSymbolAddress((void**)&agh, g_AGh);
    cudaGetSymbolAddress((void**)&agl, g_AGl);
    cudaGetSymbolAddress((void**)&x16, g_X16);
    cudaGetSymbolAddress((void**)&h16, g_H16);

    cudaFuncSetAttribute(sage_mma_kernel,
                         cudaFuncAttributeMaxDynamicSharedMemorySize,
                         2 * STAGE_B);

    const int mma_blocks  = (n_nodes + 127) / 128;
    const int agg_blocks  = (n_nodes * 32 + 255) / 256;
    const int eb = (n_edges + 255) / 256;
    const int nb = (n_nodes + 255) / 256;
    const int scan_blocks = (n_nodes + 255) / 256;
    const int wb = (256 * 512 + 255) / 256;
    const int cb = (n_nodes * 64 + 255) / 256;
    const int smem = 2 * STAGE_B;

    // ---- decode + CSR build ----
    zero_init_kernel<<<nb, 256>>>(n_nodes);
    detect_kernel<<<eb, 256>>>(raw, n_edges);
    extract_count_kernel<<<eb, 256>>>(raw, n_edges, n_nodes);
    scan_a_kernel<<<scan_blocks, 256>>>(n_nodes);
    scan_b_kernel<<<1, 256>>>(scan_blocks);
    scan_c_kernel<<<scan_blocks, 256>>>(n_nodes);
    build_kernel<<<eb, 256>>>(n_edges);

    // ---- one-time x conversion (fp16 row copy + staged planes) ----
    convert_x_kernel<<<cb, 256>>>(x, n_nodes);

    // ---- layer 1 ----
    aggregate16_kernel<<<agg_blocks, 256>>>(x16, n_nodes, agh, agl);
    prep_w_kernel<<<wb, 256>>>(W1l, W1r);
    sage_mma_kernel<<<mma_blocks, 512, smem>>>(xh, xl, b1, nullptr,
                                               hhp, hlp, h16, n_nodes, 1);

    // ---- layer 2 ----
    aggregate16_kernel<<<agg_blocks, 256>>>(h16, n_nodes, agh, agl);
    prep_w_kernel<<<wb, 256>>>(W2l, W2r);
    sage_mma_kernel<<<mma_blocks, 512, smem>>>(hhp, hlp, b2, out,
                                               nullptr, nullptr, nullptr,
                                               n_nodes, 0);
}

// round 13
// speedup vs baseline: 3.6607x; 1.3394x over previous
#include <cuda_runtime.h>
#include <cuda_fp16.h>
#include <cstdint>

#define D     256
#define MAXN  50000
#define NPAD  50048
#define MAXE  800000

// ---------------- scratch (no allocations allowed) ----------------
__device__ __align__(16) __half g_Bth[256 * 512];        // B hi, staged [s][n][16]
// A fp16 planes, staged [s<16][row][16] (dense, NPAD rows)
__device__ __align__(16) __half g_AGh[(size_t)16 * NPAD * 16];  // agg
__device__ __align__(16) __half g_Xh [(size_t)16 * NPAD * 16];  // x
__device__ __align__(16) __half g_Hh [(size_t)16 * NPAD * 16];  // h
// fp16 row-major feature copies for the gather (512B/row)
__device__ __align__(16) __half g_X16[(size_t)MAXN * D];
__device__ __align__(16) __half g_H16[(size_t)MAXN * D];
__device__ int g_cnt[MAXN];
__device__ int g_off[MAXN];
__device__ int g_pos[MAXN];
__device__ int g_bsum[256];       // per-block scan partials
__device__ int g_csr_src[MAXE];
__device__ int g_src[MAXE];
__device__ int g_tgt[MAXE];
__device__ int g_flag;            // 0 => edge dtype int64, nonzero => int32

__device__ __forceinline__ uint32_t smem_u32(const void* p) {
    uint32_t a;
    asm("{ .reg .u64 t; cvta.to.shared.u64 t, %1; cvt.u32.u64 %0, t; }"
        : "=r"(a) : "l"(p));
    return a;
}
__device__ __forceinline__ uint2 pack4(__half a, __half b, __half c, __half d) {
    uint2 r;
    r.x = (uint32_t)__half_as_ushort(a) | ((uint32_t)__half_as_ushort(b) << 16);
    r.y = (uint32_t)__half_as_ushort(c) | ((uint32_t)__half_as_ushort(d) << 16);
    return r;
}
__device__ __forceinline__ uint4 pack8(const __half* h) {
    uint4 r;
    r.x = (uint32_t)__half_as_ushort(h[0]) | ((uint32_t)__half_as_ushort(h[1]) << 16);
    r.y = (uint32_t)__half_as_ushort(h[2]) | ((uint32_t)__half_as_ushort(h[3]) << 16);
    r.z = (uint32_t)__half_as_ushort(h[4]) | ((uint32_t)__half_as_ushort(h[5]) << 16);
    r.w = (uint32_t)__half_as_ushort(h[6]) | ((uint32_t)__half_as_ushort(h[7]) << 16);
    return r;
}
__device__ __forceinline__ void add8(float* a, uint4 v) {
    float2 f;
    f = __half22float2(*(__half2*)&v.x); a[0] += f.x; a[1] += f.y;
    f = __half22float2(*(__half2*)&v.y); a[2] += f.x; a[3] += f.y;
    f = __half22float2(*(__half2*)&v.z); a[4] += f.x; a[5] += f.y;
    f = __half22float2(*(__half2*)&v.w); a[6] += f.x; a[7] += f.y;
}

// ---------------- init: zero counts + flag ----------------
__global__ void zero_init_kernel(int n) {
    int i = blockIdx.x * blockDim.x + threadIdx.x;
    if (i < n) g_cnt[i] = 0;
    if (i == 0) g_flag = 0;
}

// ---------------- edge dtype detect (sampled: 4096 edges suffice) ----------
__global__ void detect_kernel(const int* __restrict__ raw, int n_edges) {
    int checks = min(n_edges, 4096);
    for (int i = threadIdx.x; i < checks; i += blockDim.x) {
        if (raw[2 * i + 1] != 0) { atomicOr(&g_flag, 1); return; }
    }
}

// ---------------- decode + in-degree count (fused) ----------------
__global__ void extract_count_kernel(const int* __restrict__ raw,
                                     int n_edges, int n_nodes) {
    int e = blockIdx.x * blockDim.x + threadIdx.x;
    if (e >= n_edges) return;
    int s, t;
    if (g_flag == 0) {             // int64 layout: low word of each int64
        s = raw[2 * e];
        t = raw[2 * (n_edges + e)];
    } else {                       // int32 layout
        s = raw[e];
        t = raw[n_edges + e];
    }
    s = min(max(s, 0), n_nodes - 1);
    t = min(max(t, 0), n_nodes - 1);
    g_src[e] = s;
    g_tgt[e] = t;
    atomicAdd(&g_cnt[t], 1);
}

// ---------------- parallel 3-phase scan of g_cnt -> g_off, g_pos -----------
__global__ void scan_a_kernel(int n) {
    __shared__ int sh[256];
    int tid = threadIdx.x;
    int i = blockIdx.x * 256 + tid;
    int v = (i < n) ? g_cnt[i] : 0;
    sh[tid] = v;
    __syncthreads();
    #pragma unroll
    for (int off = 1; off < 256; off <<= 1) {
        int t = (tid >= off) ? sh[tid - off] : 0;
        __syncthreads();
        sh[tid] += t;
        __syncthreads();
    }
    if (i < n) g_pos[i] = sh[tid];
    if (tid == 255) g_bsum[blockIdx.x] = sh[255];
}
__global__ void scan_b_kernel(int nb) {
    __shared__ int sh[256];
    int tid = threadIdx.x;
    sh[tid] = (tid < nb) ? g_bsum[tid] : 0;
    __syncthreads();
    #pragma unroll
    for (int off = 1; off < 256; off <<= 1) {
        int t = (tid >= off) ? sh[tid - off] : 0;
        __syncthreads();
        sh[tid] += t;
        __syncthreads();
    }
    if (tid < nb) g_bsum[tid] = sh[tid];
}
__global__ void scan_c_kernel(int n) {
    int i = blockIdx.x * 256 + threadIdx.x;
    if (i >= n) return;
    int base = blockIdx.x ? g_bsum[blockIdx.x - 1] : 0;
    int off = base + g_pos[i] - g_cnt[i];
    g_off[i] = off;
    g_pos[i] = off;
}

__global__ void build_kernel(int n_edges) {
    int e = blockIdx.x * blockDim.x + threadIdx.x;
    if (e < n_edges) {
        int p = atomicAdd(&g_pos[g_tgt[e]], 1);
        g_csr_src[p] = g_src[e];
    }
}

// ---------------- one-time x -> fp16 row copy + staged plane ----------------
__global__ void convert_x_kernel(const float* __restrict__ x, int n_nodes) {
    int t = blockIdx.x * blockDim.x + threadIdx.x;
    if (t >= n_nodes * 64) return;
    int row = t >> 6;
    int g   = t & 63;                  // k0 = 4g
    float4 v = *(const float4*)(x + (size_t)row * D + g * 4);
    uint2 h = pack4(__float2half_rn(v.x), __float2half_rn(v.y),
                    __float2half_rn(v.z), __float2half_rn(v.w));
    size_t off = ((size_t)(g >> 2) * NPAD + row) * 16 + (g & 3) * 4;
    *(uint2*)(g_Xh + off) = h;
    *(uint2*)(g_X16 + (size_t)row * D + g * 4) = h;
}

// ---------------- gather mean-aggregate over fp16 rows (512B/row) ----------
__global__ void __launch_bounds__(256)
aggregate16_kernel(const __half* __restrict__ feat, int n_nodes,
                   __half* __restrict__ outh) {
    int warp = (blockIdx.x * blockDim.x + threadIdx.x) >> 5;
    int lane = threadIdx.x & 31;
    if (warp >= n_nodes) return;

    int beg = g_off[warp];
    int deg = g_cnt[warp];

    float acc[8] = {0.f, 0.f, 0.f, 0.f, 0.f, 0.f, 0.f, 0.f};
    int i = 0;
    for (; i + 4 <= deg; i += 4) {
        int s0 = __ldg(&g_csr_src[beg + i]);
        int s1 = __ldg(&g_csr_src[beg + i + 1]);
        int s2 = __ldg(&g_csr_src[beg + i + 2]);
        int s3 = __ldg(&g_csr_src[beg + i + 3]);
        uint4 v0 = *(const uint4*)(feat + (size_t)s0 * D + lane * 8);
        uint4 v1 = *(const uint4*)(feat + (size_t)s1 * D + lane * 8);
        uint4 v2 = *(const uint4*)(feat + (size_t)s2 * D + lane * 8);
        uint4 v3 = *(const uint4*)(feat + (size_t)s3 * D + lane * 8);
        add8(acc, v0); add8(acc, v1); add8(acc, v2); add8(acc, v3);
    }
    for (; i < deg; i++) {
        int s0 = __ldg(&g_csr_src[beg + i]);
        uint4 v0 = *(const uint4*)(feat + (size_t)s0 * D + lane * 8);
        add8(acc, v0);
    }

    float iv = 1.0f / (float)(deg > 1 ? deg : 1);
    __half h[8];
    #pragma unroll
    for (int j = 0; j < 8; j++) h[j] = __float2half_rn(acc[j] * iv);

    const int sp = lane >> 1;
    const int kk = (lane & 1) * 8;
    *(uint4*)(outh + ((size_t)sp * NPAD + warp) * 16 + kk) = pack8(h);
}

// ---------------- W prep: [Wl;Wr]^T -> fp16, staged [s][n][16] -------------
__global__ void prep_w_kernel(const float* __restrict__ Wl,
                              const float* __restrict__ Wr) {
    int tid = blockIdx.x * blockDim.x + threadIdx.x;
    if (tid >= 256 * 512) return;
    int k = tid & 511;
    int n = tid >> 9;
    float v = (k < 256) ? Wl[(size_t)k * 256 + n]
                        : Wr[(size_t)(k - 256) * 256 + n];
    g_Bth[(k >> 4) * 4096 + n * 16 + (k & 15)] = __float2half_rn(v);
}

// ---------------- mma.sync fp16 GEMM (1 pass, fp32 accum) ------------------
// CTA 128x256, K=512, 32 stages BK=16, 512 thr = 16 warps (4x4), warp 32x64.
// Stage smem: A[128][24h] B[256][24h] = 18432B, x2 buffers.
#define STAGE_B 18432

#define LDSM4(r, addr)                                                      \
    asm volatile("ldmatrix.sync.aligned.m8n8.x4.shared.b16 "                \
                 "{%0,%1,%2,%3}, [%4];"                                     \
                 : "=r"((r)[0]), "=r"((r)[1]), "=r"((r)[2]), "=r"((r)[3])   \
                 : "r"(addr))

#define MMA16(cc, a, b0, b1)                                                \
    asm volatile("mma.sync.aligned.m16n8k16.row.col.f32.f16.f16.f32 "       \
                 "{%0,%1,%2,%3},{%4,%5,%6,%7},{%8,%9},{%0,%1,%2,%3};"       \
                 : "+f"((cc)[0]), "+f"((cc)[1]), "+f"((cc)[2]), "+f"((cc)[3]) \
                 : "r"((a)[0]), "r"((a)[1]), "r"((a)[2]), "r"((a)[3]),      \
                   "r"(b0), "r"(b1))

__global__ void __launch_bounds__(512, 1)
sage_mma_kernel(const __half* __restrict__ inh,
                const float* __restrict__ bias, float* __restrict__ outf,
                __half* __restrict__ hh, __half* __restrict__ h16,
                int n_nodes, int do_relu) {
    extern __shared__ __align__(1024) char sm[];
    const uint32_t smb = smem_u32(sm);
    const int tid  = threadIdx.x;
    const int lane = tid & 31;
    const int wid  = tid >> 5;
    const int wm   = wid & 3;
    const int wn   = wid >> 2;
    const int row0 = blockIdx.x * 128;

    // staging: threads 0..255 stage one 16B A chunk; all 512 stage one 16B B chunk
    const bool hasA = tid < 256;
    const int  rowA = (tid & 255) >> 1;
    const int  halfA = tid & 1;
    const int  nB   = tid >> 1;            // 0..255
    const int  halfB = tid & 1;
    const uint32_t aDst = rowA * 48u + halfA * 16u;
    const uint32_t bDst = 6144u + nB * 48u + halfB * 16u;

    // ldmatrix lane addressing (48B rows)
    const uint32_t aOff = (uint32_t)(wm * 32 + (lane & 7) + 8 * ((lane >> 3) & 1)) * 48
                        + (((uint32_t)lane >> 4) << 4);
    const uint32_t bOff = (uint32_t)(wn * 64 + ((lane >> 4) << 3) + (lane & 7)) * 48
                        + ((((uint32_t)lane >> 3) & 1) << 4);

    float c[2][8][4];
    #pragma unroll
    for (int t = 0; t < 2; t++)
        #pragma unroll
        for (int nt = 0; nt < 8; nt++)
            #pragma unroll
            for (int j = 0; j < 4; j++) c[t][nt][j] = 0.f;

    uint4 ra, rb;
    auto ldg = [&](int s) {
        if (hasA) {
            const __half* srcA = (s < 16) ? g_AGh : inh;
            const int ss = s & 15;
            ra = *(const uint4*)(srcA + ((size_t)ss * NPAD + row0 + rowA) * 16
                                 + halfA * 8);
        }
        rb = *(const uint4*)(g_Bth + s * 4096 + nB * 16 + halfB * 8);
    };
    auto sts = [&](int buf) {
        char* bb = sm + buf * STAGE_B;
        if (hasA) *(uint4*)(bb + aDst) = ra;
        *(uint4*)(bb + bDst) = rb;
    };
    auto compute = [&](int buf) {
        const uint32_t bb = smb + buf * STAGE_B;
        uint32_t ah[2][4];
        LDSM4(ah[0], bb + aOff);
        LDSM4(ah[1], bb + aOff + 768);
        #pragma unroll
        for (int nt2 = 0; nt2 < 4; nt2++) {
            uint32_t bh[4];
            LDSM4(bh, bb + 6144 + bOff + nt2 * 768);
            #pragma unroll
            for (int t = 0; t < 2; t++) {
                MMA16(c[t][nt2 * 2],     ah[t], bh[0], bh[1]);
                MMA16(c[t][nt2 * 2 + 1], ah[t], bh[2], bh[3]);
            }
        }
    };

    // prologue
    ldg(0);
    sts(0);
    ldg(1);
    __syncthreads();

    #pragma unroll 1
    for (int s = 0; s < 32; s++) {
        compute(s & 1);
        if (s + 1 < 32) {
            sts((s + 1) & 1);          // write buffer not being read
            if (s + 2 < 32) ldg(s + 2);
        }
        __syncthreads();
    }

    // ---- epilogue ----
    #pragma unroll
    for (int t = 0; t < 2; t++) {
        const int r1 = row0 + wm * 32 + t * 16 + (lane >> 2);
        #pragma unroll
        for (int nt = 0; nt < 8; nt++) {
            const int col = wn * 64 + nt * 8 + 2 * (lane & 3);
            float2 b2 = *(const float2*)(bias + col);
            float v0 = c[t][nt][0] + b2.x;
            float v1 = c[t][nt][1] + b2.y;
            float v2 = c[t][nt][2] + b2.x;
            float v3 = c[t][nt][3] + b2.y;
            if (do_relu) {
                v0 = fmaxf(v0, 0.f); v1 = fmaxf(v1, 0.f);
                v2 = fmaxf(v2, 0.f); v3 = fmaxf(v3, 0.f);
            }
            const int sp = col >> 4, kk = col & 15;
            if (r1 < n_nodes) {
                if (outf)
                    *(float2*)(outf + (size_t)r1 * D + col) = make_float2(v0, v1);
                if (hh) {
                    uint32_t hi2 =
                        (uint32_t)__half_as_ushort(__float2half_rn(v0)) |
                        ((uint32_t)__half_as_ushort(__float2half_rn(v1)) << 16);
                    *(uint32_t*)(hh + ((size_t)sp * NPAD + r1) * 16 + kk) = hi2;
                    *(uint32_t*)(h16 + (size_t)r1 * D + col) = hi2;
                }
            }
            if (r1 + 8 < n_nodes) {
                if (outf)
                    *(float2*)(outf + (size_t)(r1 + 8) * D + col) = make_float2(v2, v3);
                if (hh) {
                    uint32_t hi2 =
                        (uint32_t)__half_as_ushort(__float2half_rn(v2)) |
                        ((uint32_t)__half_as_ushort(__float2half_rn(v3)) << 16);
                    *(uint32_t*)(hh + ((size_t)sp * NPAD + r1 + 8) * 16 + kk) = hi2;
                    *(uint32_t*)(h16 + (size_t)(r1 + 8) * D + col) = hi2;
                }
            }
        }
    }
}

// ---------------- launch ----------------
extern "C" void kernel_launch(void* const* d_in, const int* in_sizes, int n_in,
                              void* d_out, int out_size) {
    const float* x   = (const float*)d_in[0];
    const int*   raw = (const int*)d_in[1];
    const float* W1l = (const float*)d_in[2];
    const float* b1  = (const float*)d_in[3];
    const float* W1r = (const float*)d_in[4];
    const float* W2l = (const float*)d_in[5];
    const float* b2  = (const float*)d_in[6];
    const float* W2r = (const float*)d_in[7];
    float* out = (float*)d_out;

    const int n_nodes = in_sizes[0] / D;
    const int n_edges = in_sizes[1] / 2;

    __half *xh, *hhp, *agh, *x16, *h16;
    cudaGetSymbolAddress((void**)&xh,  g_Xh);
    cudaGetSymbolAddress((void**)&hhp, g_Hh);
    cudaGetSymbolAddress((void**)&agh, g_AGh);
    cudaGetSymbolAddress((void**)&x16, g_X16);
    cudaGetSymbolAddress((void**)&h16, g_H16);

    cudaFuncSetAttribute(sage_mma_kernel,
                         cudaFuncAttributeMaxDynamicSharedMemorySize,
                         2 * STAGE_B);

    const int mma_blocks  = (n_nodes + 127) / 128;
    const int agg_blocks  = (n_nodes * 32 + 255) / 256;
    const int eb = (n_edges + 255) / 256;
    const int nb = (n_nodes + 255) / 256;
    const int scan_blocks = (n_nodes + 255) / 256;
    const int wb = (256 * 512 + 255) / 256;
    const int cb = (n_nodes * 64 + 255) / 256;
    const int smem = 2 * STAGE_B;

    // ---- decode + CSR build ----
    zero_init_kernel<<<nb, 256>>>(n_nodes);
    detect_kernel<<<1, 1024>>>(raw, n_edges);
    extract_count_kernel<<<eb, 256>>>(raw, n_edges, n_nodes);
    scan_a_kernel<<<scan_blocks, 256>>>(n_nodes);
    scan_b_kernel<<<1, 256>>>(scan_blocks);
    scan_c_kernel<<<scan_blocks, 256>>>(n_nodes);
    build_kernel<<<eb, 256>>>(n_edges);

    // ---- one-time x conversion (fp16 row copy + staged plane) ----
    convert_x_kernel<<<cb, 256>>>(x, n_nodes);

    // ---- layer 1 ----
    aggregate16_kernel<<<agg_blocks, 256>>>(x16, n_nodes, agh);
    prep_w_kernel<<<wb, 256>>>(W1l, W1r);
    sage_mma_kernel<<<mma_blocks, 512, smem>>>(xh, b1, nullptr,
                                               hhp, h16, n_nodes, 1);

    // ---- layer 2 ----
    aggregate16_kernel<<<agg_blocks, 256>>>(h16, n_nodes, agh);
    prep_w_kernel<<<wb, 256>>>(W2l, W2r);
    sage_mma_kernel<<<mma_blocks, 512, smem>>>(hhp, b2, out,
                                               nullptr, nullptr, n_nodes, 0);
}